// round 14
// baseline (speedup 1.0000x reference)
#include <cuda_runtime.h>
#include <cuda_bf16.h>
#include <cstdint>

#define DIN  1024
#define DK2  2048      // [hi | lo] dedup split-K
#define DM   8192      // B*S
#define NH   16
#define HD   64
#define SEQ  2048
#define QSCALE 0.18033688011112042f   // 0.125 * log2(e)

#if defined(__CUDA_ARCH_FEAT_SM103_ALL) || defined(__CUDA_ARCH_FEAT_SM100_ALL)
#define HAS_TCGEN05 1
#else
#define HAS_TCGEN05 0
#endif

// ---------------- scratch (device globals: allocation-free) ----------------
__device__ float g_q[DM * DIN];              // fallback path only
__device__ float g_k[DM * DIN];
__device__ float g_v[DM * DIN];
__device__ __nv_bfloat16 g_x2[DM * DK2];     // [hi | lo]
__device__ __nv_bfloat16 g_c2[DM * DK2];     // ctx split (attn epilogue writes)
__device__ __nv_bfloat16 g_wq2[DIN * DK2];
__device__ __nv_bfloat16 g_wk2[DIN * DK2];
__device__ __nv_bfloat16 g_wv2[DIN * DK2];
__device__ __nv_bfloat16 g_wo2[DIN * DK2];
__device__ char g_kimg[64u * 32u * 16384u];
__device__ char g_vimg[64u * 32u * 16384u];
__device__ char g_qimg[64u * 16u * 32768u];

// ==================== helpers ====================
__device__ __forceinline__ uint32_t smem_to_u32(const void* p) {
    uint32_t a;
    asm("{ .reg .u64 t; cvta.to.shared.u64 t, %1; cvt.u32.u64 %0, t; }" : "=r"(a) : "l"(p));
    return a;
}
#define SMEM_SWIZZLE_128B(o) ((o) ^ (((o) >> 3) & 0x70))

__device__ __forceinline__ float ex2f(float x) {
    float r;
    asm("ex2.approx.f32 %0, %1;" : "=f"(r) : "f"(x));
    return r;
}

#if HAS_TCGEN05
__device__ __forceinline__ uint32_t elect_one_pred() {
    uint32_t pred;
    asm volatile("{\n\t.reg .pred p;\n\telect.sync _|p, 0xFFFFFFFF;\n\t"
                 "selp.b32 %0, 1, 0, p;\n\t}" : "=r"(pred));
    return pred;
}

static constexpr uint64_t SMEM_DESC_BASE_SW128 =
    (uint64_t(2) << 61) | (uint64_t(1) << 46) | (uint64_t(64) << 32) | (uint64_t(1) << 16);
#define MAKE_SMEM_DESC(a) (SMEM_DESC_BASE_SW128 | ((uint64_t)((a) >> 4) & 0x3FFF))

#define TCGEN05_ALLOC(sr, n) \
    asm volatile("tcgen05.alloc.cta_group::1.sync.aligned.shared::cta.b32 [%0], %1;" \
                 :: "r"((uint32_t)(sr)), "r"((uint32_t)(n)) : "memory")
#define TCGEN05_DEALLOC(t, n) \
    asm volatile("tcgen05.dealloc.cta_group::1.sync.aligned.b32 %0, %1;" :: "r"(t), "r"((uint32_t)(n)))
#define TCGEN05_RELINQUISH() \
    asm volatile("tcgen05.relinquish_alloc_permit.cta_group::1.sync.aligned;")
#define TCGEN05_COMMIT(mb) \
    asm volatile("tcgen05.commit.cta_group::1.mbarrier::arrive::one.shared::cluster.b64 [%0];" \
                 :: "r"((uint32_t)(mb)) : "memory")
#define TCGEN05_WAIT_LD()  asm volatile("tcgen05.wait::ld.sync.aligned;" ::: "memory")
#define TCGEN05_WAIT_ST()  asm volatile("tcgen05.wait::st.sync.aligned;" ::: "memory")
#define TCGEN05_FENCE_BEFORE() asm volatile("tcgen05.fence::before_thread_sync;" ::: "memory")
#define TCGEN05_FENCE_AFTER()  asm volatile("tcgen05.fence::after_thread_sync;" ::: "memory")
#define FENCE_ASYNC() asm volatile("fence.proxy.async.shared::cta;" ::: "memory")

#define CP_ASYNC16(dst, src) \
    asm volatile("cp.async.cg.shared.global [%0], [%1], 16;" \
                 :: "r"((uint32_t)(dst)), "l"(src) : "memory")
#define CP_COMMIT() asm volatile("cp.async.commit_group;" ::: "memory")
#define CP_WAIT(n)  asm volatile("cp.async.wait_group %0;" :: "n"(n) : "memory")

#define MBARRIER_INIT(mb, c) \
    asm volatile("mbarrier.init.shared.b64 [%0], %1;" :: "r"((uint32_t)(mb)), "r"((uint32_t)(c)) : "memory")
#define MBARRIER_INVAL(mb) \
    asm volatile("mbarrier.inval.shared.b64 [%0];" :: "r"((uint32_t)(mb)) : "memory")
#define MBARRIER_WAIT_PARITY(mb, ph) do { \
    uint32_t _mb = (uint32_t)(mb), _p = (uint32_t)(ph), _d; \
    asm volatile("{\n\t.reg .pred p;\n\t" \
        "mbarrier.try_wait.parity.acquire.cta.shared::cta.b64 p, [%1], %2;\n\t" \
        "selp.b32 %0, 1, 0, p;\n\t}" : "=r"(_d) : "r"(_mb), "r"(_p) : "memory"); \
    if (!_d) { \
        asm volatile("{\n\t.reg .pred P1;\n\tWL_%=:\n\t" \
            "mbarrier.try_wait.parity.acquire.cta.shared::cta.b64 P1, [%0], %1, 0x989680;\n\t" \
            "@P1 bra.uni WD_%=;\n\tbra.uni WL_%=;\n\tWD_%=:\n\t}" \
            :: "r"(_mb), "r"(_p) : "memory"); \
    } } while (0)

#define TCGEN05_LD_X32(r, a) \
    asm volatile("tcgen05.ld.sync.aligned.32x32b.x32.b32 " \
        "{%0,%1,%2,%3,%4,%5,%6,%7,%8,%9,%10,%11,%12,%13,%14,%15," \
        "%16,%17,%18,%19,%20,%21,%22,%23,%24,%25,%26,%27,%28,%29,%30,%31}, [%32];" \
        : "=r"((r)[0]),"=r"((r)[1]),"=r"((r)[2]),"=r"((r)[3]),"=r"((r)[4]),"=r"((r)[5]), \
          "=r"((r)[6]),"=r"((r)[7]),"=r"((r)[8]),"=r"((r)[9]),"=r"((r)[10]),"=r"((r)[11]), \
          "=r"((r)[12]),"=r"((r)[13]),"=r"((r)[14]),"=r"((r)[15]),"=r"((r)[16]),"=r"((r)[17]), \
          "=r"((r)[18]),"=r"((r)[19]),"=r"((r)[20]),"=r"((r)[21]),"=r"((r)[22]),"=r"((r)[23]), \
          "=r"((r)[24]),"=r"((r)[25]),"=r"((r)[26]),"=r"((r)[27]),"=r"((r)[28]),"=r"((r)[29]), \
          "=r"((r)[30]),"=r"((r)[31]) : "r"(a))

#define TCGEN05_LD_X16(r, a) \
    asm volatile("tcgen05.ld.sync.aligned.32x32b.x16.b32 " \
        "{%0,%1,%2,%3,%4,%5,%6,%7,%8,%9,%10,%11,%12,%13,%14,%15}, [%16];" \
        : "=r"((r)[0]),"=r"((r)[1]),"=r"((r)[2]),"=r"((r)[3]),"=r"((r)[4]),"=r"((r)[5]), \
          "=r"((r)[6]),"=r"((r)[7]),"=r"((r)[8]),"=r"((r)[9]),"=r"((r)[10]),"=r"((r)[11]), \
          "=r"((r)[12]),"=r"((r)[13]),"=r"((r)[14]),"=r"((r)[15]) : "r"(a))

#define TCGEN05_ST_X8(a, r) \
    asm volatile("tcgen05.st.sync.aligned.32x32b.x8.b32 [%0], " \
        "{%1,%2,%3,%4,%5,%6,%7,%8};" \
        :: "r"(a), "r"((r)[0]), "r"((r)[1]), "r"((r)[2]), "r"((r)[3]), \
           "r"((r)[4]), "r"((r)[5]), "r"((r)[6]), "r"((r)[7]) : "memory")

__device__ __forceinline__ void mma_f16_ss(uint32_t d, uint64_t a, uint64_t b,
                                           uint32_t idesc, bool acc) {
    uint32_t en = acc ? 1u : 0u;
    asm volatile("{\n\t.reg .pred p;\n\tsetp.ne.u32 p, %5, 0;\n\t"
                 "tcgen05.mma.cta_group::1.kind::f16 [%0], %1, %2, %3, {%4,%4,%4,%4}, p;\n\t}"
                 :: "r"(d), "l"(a), "l"(b), "r"(idesc), "r"(0u), "r"(en) : "memory");
}
__device__ __forceinline__ void mma_f16_ts(uint32_t d, uint32_t a_tmem, uint64_t b,
                                           uint32_t idesc, bool acc) {
    uint32_t en = acc ? 1u : 0u;
    asm volatile("{\n\t.reg .pred p;\n\tsetp.ne.u32 p, %5, 0;\n\t"
                 "tcgen05.mma.cta_group::1.kind::f16 [%0], [%1], %2, %3, {%4,%4,%4,%4}, p;\n\t}"
                 :: "r"(d), "r"(a_tmem), "l"(b), "r"(idesc), "r"(0u), "r"(en) : "memory");
}
#endif  // HAS_TCGEN05

// ==================== fp32 -> [hi|lo] bf16 split (merged x + weights) ======
__global__ __launch_bounds__(256) void split_all(const float* __restrict__ x,
                                                 const float* __restrict__ Wq,
                                                 const float* __restrict__ Wk,
                                                 const float* __restrict__ Wv,
                                                 const float* __restrict__ Wo) {
    const float* src; __nv_bfloat16* dst; size_t blk;
    if (blockIdx.x < 8192) { src = x; dst = g_x2; blk = blockIdx.x; }
    else {
        int w = (blockIdx.x - 8192) >> 10;
        blk = (blockIdx.x - 8192) & 1023;
        switch (w) {
            case 0: src = Wq; dst = g_wq2; break;
            case 1: src = Wk; dst = g_wk2; break;
            case 2: src = Wv; dst = g_wv2; break;
            default: src = Wo; dst = g_wo2; break;
        }
    }
    size_t i = (blk * 256 + threadIdx.x) * 4;
    size_t row = i >> 10;
    int    col = (int)(i & 1023);
    float4 v = *(const float4*)(src + i);
    float f[4] = {v.x, v.y, v.z, v.w};
    __nv_bfloat16 h[4], l[4];
#pragma unroll
    for (int j = 0; j < 4; j++) {
        h[j] = __float2bfloat16_rn(f[j]);
        l[j] = __float2bfloat16_rn(f[j] - __bfloat162float(h[j]));
    }
    __nv_bfloat16* base = dst + row * DK2 + col;
    *(uint2*)(base)        = *(uint2*)h;
    *(uint2*)(base + 1024) = *(uint2*)l;
}

// ==================== tcgen05 projection GEMM: 256x256 tile, TMEM 512 ======
#define GEMM_CHUNKS 16
#define A_OFF0 1024
#define A_OFF1 (1024 + 32768)
#define B_OFF  (1024 + 65536)
#define GEMM_SMEM (1024 + 65536 + 131072)   // 197632
#define GEMM_IDESC 0x8400490u

__device__ __forceinline__ void gemm_core(const __nv_bfloat16* __restrict__ A,
                                          const __nv_bfloat16* __restrict__ B,
                                          float* __restrict__ C,
                                          const float* __restrict__ bias,
                                          int mode) {
#if HAS_TCGEN05
    extern __shared__ char smem[];
    const uint32_t sb = smem_to_u32(smem);
    const int tid = threadIdx.x, wid = tid >> 5, lid = tid & 31;
    const int bm = blockIdx.y * 256;
    const int bn = blockIdx.x * 256;

    const uint32_t TM_PTR = sb, MBH0 = sb + 8, MBH1 = sb + 16;

    if (wid == 0) { TCGEN05_ALLOC(TM_PTR, 512); TCGEN05_RELINQUISH(); }
    if (tid == 0) { MBARRIER_INIT(MBH0, 1); MBARRIER_INIT(MBH1, 1); }
    __syncthreads();
    uint32_t tmem;
    asm volatile("ld.shared.b32 %0, [%1];" : "=r"(tmem) : "r"(TM_PTR));

    auto issue_A = [&](int half, int c) {
        const uint32_t ab = sb + (half ? A_OFF1 : A_OFF0);
        const __nv_bfloat16* Ap = A + (size_t)(bm + half * 128) * DK2 + c * 64;
#pragma unroll
        for (int i = 0; i < 4; i++) {
            int lin = tid + i * 256;
            int row = lin >> 3, q = lin & 7;
            uint32_t sw = SMEM_SWIZZLE_128B(row * 128 + q * 16);
            CP_ASYNC16(ab + sw,         Ap + (size_t)row * DK2 + q * 8);
            CP_ASYNC16(ab + 16384 + sw, Ap + (size_t)row * DK2 + 1024 + q * 8);
        }
    };
    auto issue_B = [&](int c) {
        const uint32_t bb = sb + B_OFF + (c & 1) * 65536;
        const __nv_bfloat16* Bp = B + (size_t)bn * DK2 + c * 64;
#pragma unroll
        for (int i = 0; i < 8; i++) {
            int lin = tid + i * 256;
            int row = lin >> 3, q = lin & 7;
            uint32_t sw = SMEM_SWIZZLE_128B(row * 128 + q * 16);
            CP_ASYNC16(bb + sw,         Bp + (size_t)row * DK2 + q * 8);
            CP_ASYNC16(bb + 32768 + sw, Bp + (size_t)row * DK2 + 1024 + q * 8);
        }
    };
    auto issue_mma = [&](int half, int c) {
        const uint32_t ab = sb + (half ? A_OFF1 : A_OFF0);
        const uint32_t bb = sb + B_OFF + (c & 1) * 65536;
        uint64_t ah = MAKE_SMEM_DESC(ab), al = MAKE_SMEM_DESC(ab + 16384);
        uint64_t bh = MAKE_SMEM_DESC(bb), bl = MAKE_SMEM_DESC(bb + 32768);
        const uint32_t D = tmem + half * 256;
#pragma unroll
        for (int k = 0; k < 4; k++)
            mma_f16_ss(D, ah + k * 2, bh + k * 2, GEMM_IDESC, !(c == 0 && k == 0));
#pragma unroll
        for (int k = 0; k < 4; k++)
            mma_f16_ss(D, al + k * 2, bh + k * 2, GEMM_IDESC, true);
#pragma unroll
        for (int k = 0; k < 4; k++)
            mma_f16_ss(D, ah + k * 2, bl + k * 2, GEMM_IDESC, true);
    };

    issue_A(0, 0); CP_COMMIT();
    issue_B(0);    CP_COMMIT();
    issue_A(1, 0); CP_COMMIT();
    issue_B(1);    CP_COMMIT();

    int ph0 = 0, ph1 = 0;
    for (int c = 0; c < GEMM_CHUNKS; c++) {
        if (c >= 1) {
            MBARRIER_WAIT_PARITY(MBH1, ph1 & 1); ph1++;
            issue_A(1, c); CP_COMMIT();
            if (c + 1 < GEMM_CHUNKS) issue_B(c + 1);
            CP_COMMIT();
        }
        CP_WAIT(2);
        FENCE_ASYNC();
        TCGEN05_FENCE_BEFORE();
        __syncthreads();
        if (wid == 0 && elect_one_pred()) {
            TCGEN05_FENCE_AFTER();
            issue_mma(0, c);
            TCGEN05_COMMIT(MBH0);
        }
        CP_WAIT(1);
        FENCE_ASYNC();
        TCGEN05_FENCE_BEFORE();
        __syncthreads();
        if (wid == 0 && elect_one_pred()) {
            TCGEN05_FENCE_AFTER();
            issue_mma(1, c);
            TCGEN05_COMMIT(MBH1);
        }
        MBARRIER_WAIT_PARITY(MBH0, ph0 & 1); ph0++;
        if (c + 1 < GEMM_CHUNKS) issue_A(0, c + 1);
        CP_COMMIT();
    }
    MBARRIER_WAIT_PARITY(MBH1, ph1 & 1); ph1++;
    TCGEN05_FENCE_AFTER();

    for (int half = 0; half < 2; half++) {
        const uint32_t D = tmem + half * 256;
        const int bmh = bm + half * 128;
        if (mode == 0) {
            if (wid < 4) {
                const int row = bmh + wid * 32 + lid;
                float* Crow = C + (size_t)row * DIN + bn;
#pragma unroll
                for (int cb = 0; cb < 256; cb += 32) {
                    uint32_t r[32];
                    TCGEN05_LD_X32(r, D + cb);
                    TCGEN05_WAIT_LD();
#pragma unroll
                    for (int j = 0; j < 32; j += 4) {
                        float4 v;
                        v.x = __uint_as_float(r[j + 0]) + bias[bn + cb + j + 0];
                        v.y = __uint_as_float(r[j + 1]) + bias[bn + cb + j + 1];
                        v.z = __uint_as_float(r[j + 2]) + bias[bn + cb + j + 2];
                        v.w = __uint_as_float(r[j + 3]) + bias[bn + cb + j + 3];
                        *(float4*)(Crow + cb + j) = v;
                    }
                }
                TCGEN05_FENCE_BEFORE();
            }
        } else {
            char* stg = smem + 1024;
            if (wid < 4) {
                const int rl = wid * 32 + lid;
                const int ktl = rl >> 6, rk = rl & 63;
#pragma unroll
                for (int cb = 0; cb < 256; cb += 32) {
                    uint32_t r[32];
                    TCGEN05_LD_X32(r, D + cb);
                    TCGEN05_WAIT_LD();
                    const int head = cb >> 6;
                    const int hd0  = cb & 63;
                    if (mode == 1) {
                        char* base = stg + head * 32768;
#pragma unroll
                        for (int c = 0; c < 32; c += 2) {
                            float f0 = __uint_as_float(r[c])     * QSCALE;
                            float f1 = __uint_as_float(r[c + 1]) * QSCALE;
                            __nv_bfloat16 hb[2], lb[2];
                            hb[0] = __float2bfloat16_rn(f0);
                            hb[1] = __float2bfloat16_rn(f1);
                            lb[0] = __float2bfloat16_rn(f0 - __bfloat162float(hb[0]));
                            lb[1] = __float2bfloat16_rn(f1 - __bfloat162float(hb[1]));
                            uint32_t off = SMEM_SWIZZLE_128B(rl * 128 + (hd0 + c) * 2);
                            *(uint32_t*)(base + off)         = *(uint32_t*)hb;
                            *(uint32_t*)(base + 16384 + off) = *(uint32_t*)lb;
                        }
                    } else if (mode == 2) {
                        char* base = stg + (head * 2 + ktl) * 16384;
#pragma unroll
                        for (int c = 0; c < 32; c += 2) {
                            float f0 = __uint_as_float(r[c]);
                            float f1 = __uint_as_float(r[c + 1]);
                            __nv_bfloat16 hb[2], lb[2];
                            hb[0] = __float2bfloat16_rn(f0);
                            hb[1] = __float2bfloat16_rn(f1);
                            lb[0] = __float2bfloat16_rn(f0 - __bfloat162float(hb[0]));
                            lb[1] = __float2bfloat16_rn(f1 - __bfloat162float(hb[1]));
                            uint32_t off = SMEM_SWIZZLE_128B(rk * 128 + (hd0 + c) * 2);
                            *(uint32_t*)(base + off)        = *(uint32_t*)hb;
                            *(uint32_t*)(base + 8192 + off) = *(uint32_t*)lb;
                        }
                    } else {
                        char* base = stg + (head * 2 + ktl) * 16384;
#pragma unroll
                        for (int c = 0; c < 32; c++) {
                            float f = __uint_as_float(r[c]);
                            __nv_bfloat16 vh = __float2bfloat16_rn(f);
                            __nv_bfloat16 vl = __float2bfloat16_rn(f - __bfloat162float(vh));
                            uint32_t toff = SMEM_SWIZZLE_128B((hd0 + c) * 128 + rk * 2);
                            *(__nv_bfloat16*)(base + toff)        = vh;
                            *(__nv_bfloat16*)(base + 8192 + toff) = vl;
                        }
                    }
                }
                TCGEN05_FENCE_BEFORE();
            }
            __syncthreads();
            const int bb = bmh >> 11;
            const int h0 = bn >> 6;
            if (mode == 1) {
                const int qt = (bmh & 2047) >> 7;
#pragma unroll
                for (int hh = 0; hh < 4; hh++) {
                    char* dst = g_qimg + (((size_t)(bb * 16 + h0 + hh)) * 16 + qt) * 32768;
                    const char* src = stg + hh * 32768;
#pragma unroll
                    for (int i2 = 0; i2 < 8; i2++)
                        *(uint4*)(dst + tid * 16 + i2 * 4096) =
                            *(const uint4*)(src + tid * 16 + i2 * 4096);
                }
            } else {
                const int kt0 = (bmh & 2047) >> 6;
                char* gimg = (mode == 2) ? g_kimg : g_vimg;
#pragma unroll
                for (int im = 0; im < 8; im++) {
                    int hh = im >> 1, kk = im & 1;
                    char* dst = gimg + (((size_t)(bb * 16 + h0 + hh)) * 32 + kt0 + kk) * 16384;
                    const char* src = stg + im * 16384;
#pragma unroll
                    for (int i2 = 0; i2 < 4; i2++)
                        *(uint4*)(dst + tid * 16 + i2 * 4096) =
                            *(const uint4*)(src + tid * 16 + i2 * 4096);
                }
            }
            __syncthreads();
        }
    }
    __syncthreads();
    if (tid == 0) { MBARRIER_INVAL(MBH0); MBARRIER_INVAL(MBH1); }
    __syncthreads();
    if (wid == 0) TCGEN05_DEALLOC(tmem, 512);
#else
    extern __shared__ char smem[];
    __nv_bfloat16* Achunk = (__nv_bfloat16*)(smem);
    const int tid = threadIdx.x;
    const int bn = blockIdx.x * 256;
    for (int half = 0; half < 2; half++) {
        const int bm = blockIdx.y * 256 + half * 128;
        float acc[128];
        const int nt = tid;
#pragma unroll
        for (int i = 0; i < 128; i++) acc[i] = 0.f;
        for (int c = 0; c < GEMM_CHUNKS; c++) {
            for (int i = tid; i < 128 * 128 / 8; i += 256) {
                int row = i / 16, q = (i % 16) * 8;
                int col = (q < 64) ? (c * 64 + q) : (1024 + c * 64 + q - 64);
                *(uint4*)&Achunk[row * 128 + q] =
                    *(const uint4*)(A + (size_t)(bm + row) * DK2 + col);
            }
            __syncthreads();
            const __nv_bfloat16* Bp = B + (size_t)(bn + nt) * DK2 + c * 64;
            for (int k = 0; k < 64; k++) {
                float bh = __bfloat162float(Bp[k]);
                float bl = __bfloat162float(Bp[1024 + k]);
                for (int m = 0; m < 128; m++) {
                    float ah = __bfloat162float(Achunk[m * 128 + k]);
                    float al = __bfloat162float(Achunk[m * 128 + 64 + k]);
                    acc[m] += ah * bh + al * bh + ah * bl;
                }
            }
            __syncthreads();
        }
        float bbv = (mode == 0) ? bias[bn + nt] : 0.f;
        float sc  = (mode == 1) ? QSCALE : 1.f;
        for (int m = 0; m < 128; m++)
            C[(size_t)(bm + m) * DIN + bn + nt] = acc[m] * sc + bbv;
        __syncthreads();
    }
#endif
}

__global__ __launch_bounds__(256) void gemm_qkv() {
    const __nv_bfloat16* B; float* C; int mode;
    if (blockIdx.z == 0)      { B = g_wq2; C = g_q; mode = 1; }
    else if (blockIdx.z == 1) { B = g_wk2; C = g_k; mode = 2; }
    else                      { B = g_wv2; C = g_v; mode = 3; }
    gemm_core(g_x2, B, C, nullptr, mode);
}
__global__ __launch_bounds__(256) void gemm_out(float* __restrict__ out,
                                                const float* __restrict__ bo) {
    gemm_core(g_c2, g_wo2, out, bo, 0);
}

// ==================== tcgen05 flash attention: 256-row q-tiles ==============
// TMEM (512): TSa0 @0 | TSa1 @64 | TSb0 @128 | TSb1 @192 | TOa @256 |
//             TOb @320 | PHa @384 | PLa @416 | PHb @448 | PLb @480
#define ATT_IDESC 0x8100490u
#define AQ  1024                    // Qa {h|l} 32K, Qb {h|l} 32K
#define AK  (AQ + 65536)
#define AV  (AK + 16384)
#define ATT_SMEM 122880             // padded: force 1 CTA/SM (full TMEM)

__global__ __launch_bounds__(256, 1) void attn_tc() {
#if HAS_TCGEN05
    extern __shared__ char smem[];
    const uint32_t sb = smem_to_u32(smem);
    const int tid = threadIdx.x;
    const int wid = tid >> 5, lane = tid & 31;
    const int qt = 7 - blockIdx.x;      // 256-row tiles, long first
    const int bh = blockIdx.y;
    const int b  = bh >> 4, h = bh & 15;
    const int qbase = b * SEQ + qt * 256;
    const int colh  = h * HD;

    const uint32_t TMP = sb, MBS = sb + 8, MBO = sb + 16;

    if (wid == 0) { TCGEN05_ALLOC(TMP, 512); TCGEN05_RELINQUISH(); }
    if (tid == 0) { MBARRIER_INIT(MBS, 1); MBARRIER_INIT(MBO, 1); }
    __syncthreads();
    uint32_t tmem;
    asm volatile("ld.shared.b32 %0, [%1];" : "=r"(tmem) : "r"(TMP));
    const uint32_t TOa = tmem + 256, TOb = tmem + 320;
    const uint32_t PHa = tmem + 384, PLa = tmem + 416;
    const uint32_t PHb = tmem + 448, PLb = tmem + 480;

    const char* qsa  = g_qimg + ((size_t)bh * 16 + 2 * qt) * 32768;
    const char* qsb  = qsa + 32768;
    const char* kimg = g_kimg + (size_t)bh * 32 * 16384;
    const char* vimg = g_vimg + (size_t)bh * 32 * 16384;

    // ---- prologue: Qa, Qb, K0, V0 ----
#pragma unroll
    for (int i = 0; i < 8; i++) {
        *(uint4*)(smem + AQ + tid * 16 + i * 4096) =
            *(const uint4*)(qsa + tid * 16 + i * 4096);
        *(uint4*)(smem + AQ + 32768 + tid * 16 + i * 4096) =
            *(const uint4*)(qsb + tid * 16 + i * 4096);
    }
#pragma unroll
    for (int i = 0; i < 4; i++) {
        *(uint4*)(smem + AK + tid * 16 + i * 4096) =
            *(const uint4*)(kimg + tid * 16 + i * 4096);
        *(uint4*)(smem + AV + tid * 16 + i * 4096) =
            *(const uint4*)(vimg + tid * 16 + i * 4096);
    }
    FENCE_ASYNC();
    TCGEN05_FENCE_BEFORE();
    __syncthreads();

    const uint64_t qha = MAKE_SMEM_DESC(sb + AQ);
    const uint64_t qla = MAKE_SMEM_DESC(sb + AQ + 16384);
    const uint64_t qhb = MAKE_SMEM_DESC(sb + AQ + 32768);
    const uint64_t qlb = MAKE_SMEM_DESC(sb + AQ + 49152);
    const uint64_t kh  = MAKE_SMEM_DESC(sb + AK), kl = MAKE_SMEM_DESC(sb + AK + 8192);
    const uint64_t vh  = MAKE_SMEM_DESC(sb + AV), vl = MAKE_SMEM_DESC(sb + AV + 8192);

    const int nkt = 4 * qt + 4;
    const int A_LAST = 4 * qt + 1;      // last iter where subtile a has work

    // S(0) for both subtiles
    if (wid == 0 && elect_one_pred()) {
        TCGEN05_FENCE_AFTER();
#pragma unroll
        for (int k = 0; k < 4; k++) mma_f16_ss(tmem, qha + k * 2, kh + k * 2, ATT_IDESC, k > 0);
#pragma unroll
        for (int k = 0; k < 4; k++) mma_f16_ss(tmem, qla + k * 2, kh + k * 2, ATT_IDESC, true);
#pragma unroll
        for (int k = 0; k < 4; k++) mma_f16_ss(tmem, qha + k * 2, kl + k * 2, ATT_IDESC, true);
#pragma unroll
        for (int k = 0; k < 4; k++) mma_f16_ss(tmem + 128, qhb + k * 2, kh + k * 2, ATT_IDESC, k > 0);
#pragma unroll
        for (int k = 0; k < 4; k++) mma_f16_ss(tmem + 128, qlb + k * 2, kh + k * 2, ATT_IDESC, true);
#pragma unroll
        for (int k = 0; k < 4; k++) mma_f16_ss(tmem + 128, qhb + k * 2, kl + k * 2, ATT_IDESC, true);
        TCGEN05_COMMIT(MBS);
    }

    uint4 kreg[4], vreg[4];
#pragma unroll
    for (int j = 0; j < 4; j++)
        kreg[j] = *(const uint4*)(kimg + 16384 + tid * 16 + j * 4096);

    const int sub  = wid >> 2;          // 0 = subtile a, 1 = subtile b
    const int wsub = wid & 3;
    const uint32_t rowoff = (uint32_t)wsub << 21;
    const uint32_t PH = sub ? PHb : PHa, PL = sub ? PLb : PLa;
    const int qg = qt * 256 + sub * 128 + wsub * 32 + lane;
    const int warp_min_qg = qt * 256 + sub * 128 + wsub * 32;
    float l_part = 0.f;
    int phS = 0, phO = 0;

    for (int i = 0; i < nkt; i++) {
        const int buf = i & 1, nbuf = (i + 1) & 1;
        const bool a_act  = (i <= A_LAST);
        const bool a_next = (i + 1 <= A_LAST);

        MBARRIER_WAIT_PARITY(MBS, phS & 1); phS++;
        TCGEN05_FENCE_AFTER();

        if (i + 1 < nkt) {
#pragma unroll
            for (int j = 0; j < 4; j++)
                *(uint4*)(smem + AK + tid * 16 + j * 4096) = kreg[j];
            FENCE_ASYNC();
            TCGEN05_FENCE_BEFORE();
        }
        __syncthreads();

        // issue S(i+1) for active subtiles into alternate buffers
        if (i + 1 < nkt && wid == 0 && elect_one_pred()) {
            TCGEN05_FENCE_AFTER();
            if (a_next) {
                const uint32_t D = tmem + nbuf * 64;
#pragma unroll
                for (int k = 0; k < 4; k++) mma_f16_ss(D, qha + k * 2, kh + k * 2, ATT_IDESC, k > 0);
#pragma unroll
                for (int k = 0; k < 4; k++) mma_f16_ss(D, qla + k * 2, kh + k * 2, ATT_IDESC, true);
#pragma unroll
                for (int k = 0; k < 4; k++) mma_f16_ss(D, qha + k * 2, kl + k * 2, ATT_IDESC, true);
            }
            {
                const uint32_t D = tmem + 128 + nbuf * 64;
#pragma unroll
                for (int k = 0; k < 4; k++) mma_f16_ss(D, qhb + k * 2, kh + k * 2, ATT_IDESC, k > 0);
#pragma unroll
                for (int k = 0; k < 4; k++) mma_f16_ss(D, qlb + k * 2, kh + k * 2, ATT_IDESC, true);
#pragma unroll
                for (int k = 0; k < 4; k++) mma_f16_ss(D, qhb + k * 2, kl + k * 2, ATT_IDESC, true);
            }
            TCGEN05_COMMIT(MBS);
        }

        if (i + 2 < nkt) {
            const char* ks = kimg + (size_t)(i + 2) * 16384;
#pragma unroll
            for (int j = 0; j < 4; j++)
                kreg[j] = *(const uint4*)(ks + tid * 16 + j * 4096);
        }

        if (i > 0) {
            MBARRIER_WAIT_PARITY(MBO, phO & 1); phO++;
            TCGEN05_FENCE_AFTER();
#pragma unroll
            for (int j = 0; j < 4; j++)
                *(uint4*)(smem + AV + tid * 16 + j * 4096) = vreg[j];
        }

        // ---- softmax for this warp's subtile (64 cols of its 32 rows) ----
        if (sub == 1 || a_act) {
            const uint32_t TS_mine = tmem + sub * 128 + buf * 64;
            const bool nomask = (i * 64 + 63) <= warp_min_qg;
#pragma unroll
            for (int hh2 = 0; hh2 < 4; hh2++) {
                uint32_t s16[16];
                TCGEN05_LD_X16(s16, TS_mine + hh2 * 16);
                TCGEN05_WAIT_LD();
                uint32_t php[8], plp[8];
                if (nomask) {
#pragma unroll
                    for (int c = 0; c < 8; c++) {
                        float p0 = ex2f(__uint_as_float(s16[2 * c]));
                        float p1 = ex2f(__uint_as_float(s16[2 * c + 1]));
                        l_part += p0 + p1;
                        __nv_bfloat16 hb2[2], lb2[2];
                        hb2[0] = __float2bfloat16_rn(p0);
                        hb2[1] = __float2bfloat16_rn(p1);
                        lb2[0] = __float2bfloat16_rn(p0 - __bfloat162float(hb2[0]));
                        lb2[1] = __float2bfloat16_rn(p1 - __bfloat162float(hb2[1]));
                        php[c] = *(uint32_t*)hb2;
                        plp[c] = *(uint32_t*)lb2;
                    }
                } else {
#pragma unroll
                    for (int c = 0; c < 8; c++) {
                        int j0 = i * 64 + hh2 * 16 + 2 * c;
                        float p0 = (j0     <= qg) ? ex2f(__uint_as_float(s16[2 * c]))     : 0.f;
                        float p1 = (j0 + 1 <= qg) ? ex2f(__uint_as_float(s16[2 * c + 1])) : 0.f;
                        l_part += p0 + p1;
                        __nv_bfloat16 hb2[2], lb2[2];
                        hb2[0] = __float2bfloat16_rn(p0);
                        hb2[1] = __float2bfloat16_rn(p1);
                        lb2[0] = __float2bfloat16_rn(p0 - __bfloat162float(hb2[0]));
                        lb2[1] = __float2bfloat16_rn(p1 - __bfloat162float(hb2[1]));
                        php[c] = *(uint32_t*)hb2;
                        plp[c] = *(uint32_t*)lb2;
                    }
                }
                TCGEN05_ST_X8(PH + hh2 * 8 + rowoff, php);
                TCGEN05_ST_X8(PL + hh2 * 8 + rowoff, plp);
            }
            TCGEN05_WAIT_ST();
        }
        FENCE_ASYNC();
        TCGEN05_FENCE_BEFORE();
        __syncthreads();

        // ---- O += P*V (TS mode) for active subtiles ----
        if (wid == 0 && elect_one_pred()) {
            TCGEN05_FENCE_AFTER();
            if (a_act) {
#pragma unroll
                for (int k = 0; k < 4; k++)
                    mma_f16_ts(TOa, PHa + k * 8, vh + k * 2, ATT_IDESC, !(i == 0 && k == 0));
#pragma unroll
                for (int k = 0; k < 4; k++)
                    mma_f16_ts(TOa, PLa + k * 8, vh + k * 2, ATT_IDESC, true);
#pragma unroll
                for (int k = 0; k < 4; k++)
                    mma_f16_ts(TOa, PHa + k * 8, vl + k * 2, ATT_IDESC, true);
            }
#pragma unroll
            for (int k = 0; k < 4; k++)
                mma_f16_ts(TOb, PHb + k * 8, vh + k * 2, ATT_IDESC, !(i == 0 && k == 0));
#pragma unroll
            for (int k = 0; k < 4; k++)
                mma_f16_ts(TOb, PLb + k * 8, vh + k * 2, ATT_IDESC, true);
#pragma unroll
            for (int k = 0; k < 4; k++)
                mma_f16_ts(TOb, PHb + k * 8, vl + k * 2, ATT_IDESC, true);
            TCGEN05_COMMIT(MBO);
        }
        if (i + 1 < nkt) {
            const char* vs = vimg + (size_t)(i + 1) * 16384;
#pragma unroll
            for (int j = 0; j < 4; j++)
                vreg[j] = *(const uint4*)(vs + tid * 16 + j * 4096);
        }
    }

    // ---- epilogue: O/l with fused [hi|lo] split store to g_c2 ----
    MBARRIER_WAIT_PARITY(MBO, phO & 1); phO++;
    TCGEN05_FENCE_AFTER();

    const float linv = 1.f / l_part;
    const uint32_t TO_mine = sub ? TOb : TOa;
    __nv_bfloat16* base =
        g_c2 + (size_t)(qbase + sub * 128 + wsub * 32 + lane) * DK2 + colh;
#pragma unroll
    for (int half = 0; half < 2; half++) {
        uint32_t orr[32];
        TCGEN05_LD_X32(orr, TO_mine + half * 32);
        TCGEN05_WAIT_LD();
#pragma unroll
        for (int c = 0; c < 32; c += 4) {
            float f[4];
            __nv_bfloat16 hh2[4], ll2[4];
#pragma unroll
            for (int e = 0; e < 4; e++) {
                f[e] = __uint_as_float(orr[c + e]) * linv;
                hh2[e] = __float2bfloat16_rn(f[e]);
                ll2[e] = __float2bfloat16_rn(f[e] - __bfloat162float(hh2[e]));
            }
            *(uint2*)(base + half * 32 + c)        = *(uint2*)hh2;
            *(uint2*)(base + 1024 + half * 32 + c) = *(uint2*)ll2;
        }
    }
    TCGEN05_FENCE_BEFORE();
    __syncthreads();
    if (tid == 0) { MBARRIER_INVAL(MBS); MBARRIER_INVAL(MBO); }
    __syncthreads();
    if (wid == 0) TCGEN05_DEALLOC(tmem, 512);
#else
    const int qt = 7 - blockIdx.x, bh = blockIdx.y;
    const int b = bh >> 4, h = bh & 15;
    for (int rr = 0; rr < 2; rr++) {
        const int r = rr * 128 + (threadIdx.x >> 1);
        const int d0 = (threadIdx.x & 1) * 32;
        const int qrow = b * SEQ + qt * 256 + r;
        const int qg = qt * 256 + r;
        const float* qp = g_q + (size_t)qrow * DIN + h * HD;
        float o[32];
#pragma unroll
        for (int dd = 0; dd < 32; dd++) o[dd] = 0.f;
        float l = 0.f;
        for (int j = 0; j <= qg; j++) {
            const float* kp = g_k + (size_t)(b * SEQ + j) * DIN + h * HD;
            float s = 0.f;
            for (int d = 0; d < 64; d++) s += qp[d] * kp[d];
            float p = exp2f(s);
            l += p;
            const float* vp = g_v + (size_t)(b * SEQ + j) * DIN + h * HD + d0;
            for (int dd = 0; dd < 32; dd++) o[dd] += p * vp[dd];
        }
        __nv_bfloat16* base = g_c2 + (size_t)qrow * DK2 + h * HD + d0;
        for (int dd = 0; dd < 32; dd++) {
            float f = o[dd] / l;
            __nv_bfloat16 hh = __float2bfloat16_rn(f);
            __nv_bfloat16 ll = __float2bfloat16_rn(f - __bfloat162float(hh));
            base[dd] = hh;
            base[1024 + dd] = ll;
        }
    }
#endif
}

// ==================== launch ====================
extern "C" void kernel_launch(void* const* d_in, const int* in_sizes, int n_in,
                              void* d_out, int out_size) {
    const float* x  = (const float*)d_in[0];
    const float* Wq = (const float*)d_in[1];
    const float* Wk = (const float*)d_in[2];
    const float* Wv = (const float*)d_in[3];
    const float* Wo = (const float*)d_in[4];
    const float* bo = (const float*)d_in[5];
    float* out = (float*)d_out;

    cudaFuncSetAttribute(attn_tc, cudaFuncAttributeMaxDynamicSharedMemorySize, ATT_SMEM);
    cudaFuncSetAttribute(gemm_qkv, cudaFuncAttributeMaxDynamicSharedMemorySize, GEMM_SMEM);
    cudaFuncSetAttribute(gemm_out, cudaFuncAttributeMaxDynamicSharedMemorySize, GEMM_SMEM);

    split_all<<<12288, 256>>>(x, Wq, Wk, Wv, Wo);
    gemm_qkv<<<dim3(4, 32, 3), 256, GEMM_SMEM>>>();
    attn_tc<<<dim3(8, 64), 256, ATT_SMEM>>>();
    gemm_out<<<dim3(4, 32), 256, GEMM_SMEM>>>(out, bo);
}

// round 15
// speedup vs baseline: 1.2043x; 1.2043x over previous
#include <cuda_runtime.h>
#include <cuda_bf16.h>
#include <cstdint>

#define DIN  1024
#define DK2  2048      // [hi | lo] dedup split-K
#define DM   8192      // B*S
#define NH   16
#define HD   64
#define SEQ  2048
#define QSCALE 0.18033688011112042f   // 0.125 * log2(e)

#if defined(__CUDA_ARCH_FEAT_SM103_ALL) || defined(__CUDA_ARCH_FEAT_SM100_ALL)
#define HAS_TCGEN05 1
#else
#define HAS_TCGEN05 0
#endif

// ---------------- scratch (device globals: allocation-free) ----------------
__device__ float g_q[DM * DIN];              // fallback path only
__device__ float g_k[DM * DIN];
__device__ float g_v[DM * DIN];
__device__ __nv_bfloat16 g_x2[DM * DK2];     // [hi | lo]
__device__ __nv_bfloat16 g_c2[DM * DK2];     // ctx split (attn epilogue writes)
__device__ __nv_bfloat16 g_wq2[DIN * DK2];
__device__ __nv_bfloat16 g_wk2[DIN * DK2];
__device__ __nv_bfloat16 g_wv2[DIN * DK2];
__device__ __nv_bfloat16 g_wo2[DIN * DK2];
__device__ char g_kimg[64u * 32u * 16384u];
__device__ char g_vimg[64u * 32u * 16384u];
__device__ char g_qimg[64u * 16u * 32768u];

// ==================== helpers ====================
__device__ __forceinline__ uint32_t smem_to_u32(const void* p) {
    uint32_t a;
    asm("{ .reg .u64 t; cvta.to.shared.u64 t, %1; cvt.u32.u64 %0, t; }" : "=r"(a) : "l"(p));
    return a;
}
#define SMEM_SWIZZLE_128B(o) ((o) ^ (((o) >> 3) & 0x70))

__device__ __forceinline__ float ex2f(float x) {
    float r;
    asm("ex2.approx.f32 %0, %1;" : "=f"(r) : "f"(x));
    return r;
}

#if HAS_TCGEN05
__device__ __forceinline__ uint32_t elect_one_pred() {
    uint32_t pred;
    asm volatile("{\n\t.reg .pred p;\n\telect.sync _|p, 0xFFFFFFFF;\n\t"
                 "selp.b32 %0, 1, 0, p;\n\t}" : "=r"(pred));
    return pred;
}

static constexpr uint64_t SMEM_DESC_BASE_SW128 =
    (uint64_t(2) << 61) | (uint64_t(1) << 46) | (uint64_t(64) << 32) | (uint64_t(1) << 16);
#define MAKE_SMEM_DESC(a) (SMEM_DESC_BASE_SW128 | ((uint64_t)((a) >> 4) & 0x3FFF))

#define TCGEN05_ALLOC(sr, n) \
    asm volatile("tcgen05.alloc.cta_group::1.sync.aligned.shared::cta.b32 [%0], %1;" \
                 :: "r"((uint32_t)(sr)), "r"((uint32_t)(n)) : "memory")
#define TCGEN05_DEALLOC(t, n) \
    asm volatile("tcgen05.dealloc.cta_group::1.sync.aligned.b32 %0, %1;" :: "r"(t), "r"((uint32_t)(n)))
#define TCGEN05_RELINQUISH() \
    asm volatile("tcgen05.relinquish_alloc_permit.cta_group::1.sync.aligned;")
#define TCGEN05_COMMIT(mb) \
    asm volatile("tcgen05.commit.cta_group::1.mbarrier::arrive::one.shared::cluster.b64 [%0];" \
                 :: "r"((uint32_t)(mb)) : "memory")
#define TCGEN05_WAIT_LD()  asm volatile("tcgen05.wait::ld.sync.aligned;" ::: "memory")
#define TCGEN05_WAIT_ST()  asm volatile("tcgen05.wait::st.sync.aligned;" ::: "memory")
#define TCGEN05_FENCE_BEFORE() asm volatile("tcgen05.fence::before_thread_sync;" ::: "memory")
#define TCGEN05_FENCE_AFTER()  asm volatile("tcgen05.fence::after_thread_sync;" ::: "memory")
#define FENCE_ASYNC() asm volatile("fence.proxy.async.shared::cta;" ::: "memory")

#define CP_ASYNC16(dst, src) \
    asm volatile("cp.async.cg.shared.global [%0], [%1], 16;" \
                 :: "r"((uint32_t)(dst)), "l"(src) : "memory")
#define CP_COMMIT() asm volatile("cp.async.commit_group;" ::: "memory")
#define CP_WAIT(n)  asm volatile("cp.async.wait_group %0;" :: "n"(n) : "memory")

#define MBARRIER_INIT(mb, c) \
    asm volatile("mbarrier.init.shared.b64 [%0], %1;" :: "r"((uint32_t)(mb)), "r"((uint32_t)(c)) : "memory")
#define MBARRIER_INVAL(mb) \
    asm volatile("mbarrier.inval.shared.b64 [%0];" :: "r"((uint32_t)(mb)) : "memory")
#define MBARRIER_WAIT_PARITY(mb, ph) do { \
    uint32_t _mb = (uint32_t)(mb), _p = (uint32_t)(ph), _d; \
    asm volatile("{\n\t.reg .pred p;\n\t" \
        "mbarrier.try_wait.parity.acquire.cta.shared::cta.b64 p, [%1], %2;\n\t" \
        "selp.b32 %0, 1, 0, p;\n\t}" : "=r"(_d) : "r"(_mb), "r"(_p) : "memory"); \
    if (!_d) { \
        asm volatile("{\n\t.reg .pred P1;\n\tWL_%=:\n\t" \
            "mbarrier.try_wait.parity.acquire.cta.shared::cta.b64 P1, [%0], %1, 0x989680;\n\t" \
            "@P1 bra.uni WD_%=;\n\tbra.uni WL_%=;\n\tWD_%=:\n\t}" \
            :: "r"(_mb), "r"(_p) : "memory"); \
    } } while (0)

#define TCGEN05_LD_X32(r, a) \
    asm volatile("tcgen05.ld.sync.aligned.32x32b.x32.b32 " \
        "{%0,%1,%2,%3,%4,%5,%6,%7,%8,%9,%10,%11,%12,%13,%14,%15," \
        "%16,%17,%18,%19,%20,%21,%22,%23,%24,%25,%26,%27,%28,%29,%30,%31}, [%32];" \
        : "=r"((r)[0]),"=r"((r)[1]),"=r"((r)[2]),"=r"((r)[3]),"=r"((r)[4]),"=r"((r)[5]), \
          "=r"((r)[6]),"=r"((r)[7]),"=r"((r)[8]),"=r"((r)[9]),"=r"((r)[10]),"=r"((r)[11]), \
          "=r"((r)[12]),"=r"((r)[13]),"=r"((r)[14]),"=r"((r)[15]),"=r"((r)[16]),"=r"((r)[17]), \
          "=r"((r)[18]),"=r"((r)[19]),"=r"((r)[20]),"=r"((r)[21]),"=r"((r)[22]),"=r"((r)[23]), \
          "=r"((r)[24]),"=r"((r)[25]),"=r"((r)[26]),"=r"((r)[27]),"=r"((r)[28]),"=r"((r)[29]), \
          "=r"((r)[30]),"=r"((r)[31]) : "r"(a))

#define TCGEN05_ST_X8(a, r) \
    asm volatile("tcgen05.st.sync.aligned.32x32b.x8.b32 [%0], " \
        "{%1,%2,%3,%4,%5,%6,%7,%8};" \
        :: "r"(a), "r"((r)[0]), "r"((r)[1]), "r"((r)[2]), "r"((r)[3]), \
           "r"((r)[4]), "r"((r)[5]), "r"((r)[6]), "r"((r)[7]) : "memory")

__device__ __forceinline__ void mma_f16_ss(uint32_t d, uint64_t a, uint64_t b,
                                           uint32_t idesc, bool acc) {
    uint32_t en = acc ? 1u : 0u;
    asm volatile("{\n\t.reg .pred p;\n\tsetp.ne.u32 p, %5, 0;\n\t"
                 "tcgen05.mma.cta_group::1.kind::f16 [%0], %1, %2, %3, {%4,%4,%4,%4}, p;\n\t}"
                 :: "r"(d), "l"(a), "l"(b), "r"(idesc), "r"(0u), "r"(en) : "memory");
}
__device__ __forceinline__ void mma_f16_ts(uint32_t d, uint32_t a_tmem, uint64_t b,
                                           uint32_t idesc, bool acc) {
    uint32_t en = acc ? 1u : 0u;
    asm volatile("{\n\t.reg .pred p;\n\tsetp.ne.u32 p, %5, 0;\n\t"
                 "tcgen05.mma.cta_group::1.kind::f16 [%0], [%1], %2, %3, {%4,%4,%4,%4}, p;\n\t}"
                 :: "r"(d), "r"(a_tmem), "l"(b), "r"(idesc), "r"(0u), "r"(en) : "memory");
}
#endif  // HAS_TCGEN05

// ==================== fp32 -> [hi|lo] bf16 split (merged x + weights) ======
__global__ __launch_bounds__(256) void split_all(const float* __restrict__ x,
                                                 const float* __restrict__ Wq,
                                                 const float* __restrict__ Wk,
                                                 const float* __restrict__ Wv,
                                                 const float* __restrict__ Wo) {
    const float* src; __nv_bfloat16* dst; size_t blk;
    if (blockIdx.x < 8192) { src = x; dst = g_x2; blk = blockIdx.x; }
    else {
        int w = (blockIdx.x - 8192) >> 10;
        blk = (blockIdx.x - 8192) & 1023;
        switch (w) {
            case 0: src = Wq; dst = g_wq2; break;
            case 1: src = Wk; dst = g_wk2; break;
            case 2: src = Wv; dst = g_wv2; break;
            default: src = Wo; dst = g_wo2; break;
        }
    }
    size_t i = (blk * 256 + threadIdx.x) * 4;
    size_t row = i >> 10;
    int    col = (int)(i & 1023);
    float4 v = *(const float4*)(src + i);
    float f[4] = {v.x, v.y, v.z, v.w};
    __nv_bfloat16 h[4], l[4];
#pragma unroll
    for (int j = 0; j < 4; j++) {
        h[j] = __float2bfloat16_rn(f[j]);
        l[j] = __float2bfloat16_rn(f[j] - __bfloat162float(h[j]));
    }
    __nv_bfloat16* base = dst + row * DK2 + col;
    *(uint2*)(base)        = *(uint2*)h;
    *(uint2*)(base + 1024) = *(uint2*)l;
}

// ==================== tcgen05 projection GEMM: 256x256 tile, TMEM 512 ======
#define GEMM_CHUNKS 16
#define A_OFF0 1024
#define A_OFF1 (1024 + 32768)
#define B_OFF  (1024 + 65536)
#define GEMM_SMEM (1024 + 65536 + 131072)   // 197632
#define GEMM_IDESC 0x8400490u

__device__ __forceinline__ void gemm_core(const __nv_bfloat16* __restrict__ A,
                                          const __nv_bfloat16* __restrict__ B,
                                          float* __restrict__ C,
                                          const float* __restrict__ bias,
                                          int mode) {
#if HAS_TCGEN05
    extern __shared__ char smem[];
    const uint32_t sb = smem_to_u32(smem);
    const int tid = threadIdx.x, wid = tid >> 5, lid = tid & 31;
    const int bm = blockIdx.y * 256;
    const int bn = blockIdx.x * 256;

    const uint32_t TM_PTR = sb, MBH0 = sb + 8, MBH1 = sb + 16;

    if (wid == 0) { TCGEN05_ALLOC(TM_PTR, 512); TCGEN05_RELINQUISH(); }
    if (tid == 0) { MBARRIER_INIT(MBH0, 1); MBARRIER_INIT(MBH1, 1); }
    __syncthreads();
    uint32_t tmem;
    asm volatile("ld.shared.b32 %0, [%1];" : "=r"(tmem) : "r"(TM_PTR));

    auto issue_A = [&](int half, int c) {
        const uint32_t ab = sb + (half ? A_OFF1 : A_OFF0);
        const __nv_bfloat16* Ap = A + (size_t)(bm + half * 128) * DK2 + c * 64;
#pragma unroll
        for (int i = 0; i < 4; i++) {
            int lin = tid + i * 256;
            int row = lin >> 3, q = lin & 7;
            uint32_t sw = SMEM_SWIZZLE_128B(row * 128 + q * 16);
            CP_ASYNC16(ab + sw,         Ap + (size_t)row * DK2 + q * 8);
            CP_ASYNC16(ab + 16384 + sw, Ap + (size_t)row * DK2 + 1024 + q * 8);
        }
    };
    auto issue_B = [&](int c) {
        const uint32_t bb = sb + B_OFF + (c & 1) * 65536;
        const __nv_bfloat16* Bp = B + (size_t)bn * DK2 + c * 64;
#pragma unroll
        for (int i = 0; i < 8; i++) {
            int lin = tid + i * 256;
            int row = lin >> 3, q = lin & 7;
            uint32_t sw = SMEM_SWIZZLE_128B(row * 128 + q * 16);
            CP_ASYNC16(bb + sw,         Bp + (size_t)row * DK2 + q * 8);
            CP_ASYNC16(bb + 32768 + sw, Bp + (size_t)row * DK2 + 1024 + q * 8);
        }
    };
    auto issue_mma = [&](int half, int c) {
        const uint32_t ab = sb + (half ? A_OFF1 : A_OFF0);
        const uint32_t bb = sb + B_OFF + (c & 1) * 65536;
        uint64_t ah = MAKE_SMEM_DESC(ab), al = MAKE_SMEM_DESC(ab + 16384);
        uint64_t bh = MAKE_SMEM_DESC(bb), bl = MAKE_SMEM_DESC(bb + 32768);
        const uint32_t D = tmem + half * 256;
#pragma unroll
        for (int k = 0; k < 4; k++)
            mma_f16_ss(D, ah + k * 2, bh + k * 2, GEMM_IDESC, !(c == 0 && k == 0));
#pragma unroll
        for (int k = 0; k < 4; k++)
            mma_f16_ss(D, al + k * 2, bh + k * 2, GEMM_IDESC, true);
#pragma unroll
        for (int k = 0; k < 4; k++)
            mma_f16_ss(D, ah + k * 2, bl + k * 2, GEMM_IDESC, true);
    };

    issue_A(0, 0); CP_COMMIT();
    issue_B(0);    CP_COMMIT();
    issue_A(1, 0); CP_COMMIT();
    issue_B(1);    CP_COMMIT();

    int ph0 = 0, ph1 = 0;
    for (int c = 0; c < GEMM_CHUNKS; c++) {
        if (c >= 1) {
            MBARRIER_WAIT_PARITY(MBH1, ph1 & 1); ph1++;
            issue_A(1, c); CP_COMMIT();
            if (c + 1 < GEMM_CHUNKS) issue_B(c + 1);
            CP_COMMIT();
        }
        CP_WAIT(2);
        FENCE_ASYNC();
        TCGEN05_FENCE_BEFORE();
        __syncthreads();
        if (wid == 0 && elect_one_pred()) {
            TCGEN05_FENCE_AFTER();
            issue_mma(0, c);
            TCGEN05_COMMIT(MBH0);
        }
        CP_WAIT(1);
        FENCE_ASYNC();
        TCGEN05_FENCE_BEFORE();
        __syncthreads();
        if (wid == 0 && elect_one_pred()) {
            TCGEN05_FENCE_AFTER();
            issue_mma(1, c);
            TCGEN05_COMMIT(MBH1);
        }
        MBARRIER_WAIT_PARITY(MBH0, ph0 & 1); ph0++;
        if (c + 1 < GEMM_CHUNKS) issue_A(0, c + 1);
        CP_COMMIT();
    }
    MBARRIER_WAIT_PARITY(MBH1, ph1 & 1); ph1++;
    TCGEN05_FENCE_AFTER();

    for (int half = 0; half < 2; half++) {
        const uint32_t D = tmem + half * 256;
        const int bmh = bm + half * 128;
        if (mode == 0) {
            if (wid < 4) {
                const int row = bmh + wid * 32 + lid;
                float* Crow = C + (size_t)row * DIN + bn;
#pragma unroll
                for (int cb = 0; cb < 256; cb += 32) {
                    uint32_t r[32];
                    TCGEN05_LD_X32(r, D + cb);
                    TCGEN05_WAIT_LD();
#pragma unroll
                    for (int j = 0; j < 32; j += 4) {
                        float4 v;
                        v.x = __uint_as_float(r[j + 0]) + bias[bn + cb + j + 0];
                        v.y = __uint_as_float(r[j + 1]) + bias[bn + cb + j + 1];
                        v.z = __uint_as_float(r[j + 2]) + bias[bn + cb + j + 2];
                        v.w = __uint_as_float(r[j + 3]) + bias[bn + cb + j + 3];
                        *(float4*)(Crow + cb + j) = v;
                    }
                }
                TCGEN05_FENCE_BEFORE();
            }
        } else {
            char* stg = smem + 1024;
            if (wid < 4) {
                const int rl = wid * 32 + lid;
                const int ktl = rl >> 6, rk = rl & 63;
#pragma unroll
                for (int cb = 0; cb < 256; cb += 32) {
                    uint32_t r[32];
                    TCGEN05_LD_X32(r, D + cb);
                    TCGEN05_WAIT_LD();
                    const int head = cb >> 6;
                    const int hd0  = cb & 63;
                    if (mode == 1) {
                        char* base = stg + head * 32768;
#pragma unroll
                        for (int c = 0; c < 32; c += 2) {
                            float f0 = __uint_as_float(r[c])     * QSCALE;
                            float f1 = __uint_as_float(r[c + 1]) * QSCALE;
                            __nv_bfloat16 hb[2], lb[2];
                            hb[0] = __float2bfloat16_rn(f0);
                            hb[1] = __float2bfloat16_rn(f1);
                            lb[0] = __float2bfloat16_rn(f0 - __bfloat162float(hb[0]));
                            lb[1] = __float2bfloat16_rn(f1 - __bfloat162float(hb[1]));
                            uint32_t off = SMEM_SWIZZLE_128B(rl * 128 + (hd0 + c) * 2);
                            *(uint32_t*)(base + off)         = *(uint32_t*)hb;
                            *(uint32_t*)(base + 16384 + off) = *(uint32_t*)lb;
                        }
                    } else if (mode == 2) {
                        char* base = stg + (head * 2 + ktl) * 16384;
#pragma unroll
                        for (int c = 0; c < 32; c += 2) {
                            float f0 = __uint_as_float(r[c]);
                            float f1 = __uint_as_float(r[c + 1]);
                            __nv_bfloat16 hb[2], lb[2];
                            hb[0] = __float2bfloat16_rn(f0);
                            hb[1] = __float2bfloat16_rn(f1);
                            lb[0] = __float2bfloat16_rn(f0 - __bfloat162float(hb[0]));
                            lb[1] = __float2bfloat16_rn(f1 - __bfloat162float(hb[1]));
                            uint32_t off = SMEM_SWIZZLE_128B(rk * 128 + (hd0 + c) * 2);
                            *(uint32_t*)(base + off)        = *(uint32_t*)hb;
                            *(uint32_t*)(base + 8192 + off) = *(uint32_t*)lb;
                        }
                    } else {
                        char* base = stg + (head * 2 + ktl) * 16384;
#pragma unroll
                        for (int c = 0; c < 32; c++) {
                            float f = __uint_as_float(r[c]);
                            __nv_bfloat16 vh = __float2bfloat16_rn(f);
                            __nv_bfloat16 vl = __float2bfloat16_rn(f - __bfloat162float(vh));
                            uint32_t toff = SMEM_SWIZZLE_128B((hd0 + c) * 128 + rk * 2);
                            *(__nv_bfloat16*)(base + toff)        = vh;
                            *(__nv_bfloat16*)(base + 8192 + toff) = vl;
                        }
                    }
                }
                TCGEN05_FENCE_BEFORE();
            }
            __syncthreads();
            const int bb = bmh >> 11;
            const int h0 = bn >> 6;
            if (mode == 1) {
                const int qt = (bmh & 2047) >> 7;
#pragma unroll
                for (int hh = 0; hh < 4; hh++) {
                    char* dst = g_qimg + (((size_t)(bb * 16 + h0 + hh)) * 16 + qt) * 32768;
                    const char* src = stg + hh * 32768;
#pragma unroll
                    for (int i2 = 0; i2 < 8; i2++)
                        *(uint4*)(dst + tid * 16 + i2 * 4096) =
                            *(const uint4*)(src + tid * 16 + i2 * 4096);
                }
            } else {
                const int kt0 = (bmh & 2047) >> 6;
                char* gimg = (mode == 2) ? g_kimg : g_vimg;
#pragma unroll
                for (int im = 0; im < 8; im++) {
                    int hh = im >> 1, kk = im & 1;
                    char* dst = gimg + (((size_t)(bb * 16 + h0 + hh)) * 32 + kt0 + kk) * 16384;
                    const char* src = stg + im * 16384;
#pragma unroll
                    for (int i2 = 0; i2 < 4; i2++)
                        *(uint4*)(dst + tid * 16 + i2 * 4096) =
                            *(const uint4*)(src + tid * 16 + i2 * 4096);
                }
            }
            __syncthreads();
        }
    }
    __syncthreads();
    if (tid == 0) { MBARRIER_INVAL(MBH0); MBARRIER_INVAL(MBH1); }
    __syncthreads();
    if (wid == 0) TCGEN05_DEALLOC(tmem, 512);
#else
    extern __shared__ char smem[];
    __nv_bfloat16* Achunk = (__nv_bfloat16*)(smem);
    const int tid = threadIdx.x;
    const int bn = blockIdx.x * 256;
    for (int half = 0; half < 2; half++) {
        const int bm = blockIdx.y * 256 + half * 128;
        float acc[128];
        const int nt = tid;
#pragma unroll
        for (int i = 0; i < 128; i++) acc[i] = 0.f;
        for (int c = 0; c < GEMM_CHUNKS; c++) {
            for (int i = tid; i < 128 * 128 / 8; i += 256) {
                int row = i / 16, q = (i % 16) * 8;
                int col = (q < 64) ? (c * 64 + q) : (1024 + c * 64 + q - 64);
                *(uint4*)&Achunk[row * 128 + q] =
                    *(const uint4*)(A + (size_t)(bm + row) * DK2 + col);
            }
            __syncthreads();
            const __nv_bfloat16* Bp = B + (size_t)(bn + nt) * DK2 + c * 64;
            for (int k = 0; k < 64; k++) {
                float bh = __bfloat162float(Bp[k]);
                float bl = __bfloat162float(Bp[1024 + k]);
                for (int m = 0; m < 128; m++) {
                    float ah = __bfloat162float(Achunk[m * 128 + k]);
                    float al = __bfloat162float(Achunk[m * 128 + 64 + k]);
                    acc[m] += ah * bh + al * bh + ah * bl;
                }
            }
            __syncthreads();
        }
        float bbv = (mode == 0) ? bias[bn + nt] : 0.f;
        float sc  = (mode == 1) ? QSCALE : 1.f;
        for (int m = 0; m < 128; m++)
            C[(size_t)(bm + m) * DIN + bn + nt] = acc[m] * sc + bbv;
        __syncthreads();
    }
#endif
}

__global__ __launch_bounds__(256) void gemm_qkv() {
    const __nv_bfloat16* B; float* C; int mode;
    if (blockIdx.z == 0)      { B = g_wq2; C = g_q; mode = 1; }
    else if (blockIdx.z == 1) { B = g_wk2; C = g_k; mode = 2; }
    else                      { B = g_wv2; C = g_v; mode = 3; }
    gemm_core(g_x2, B, C, nullptr, mode);
}
__global__ __launch_bounds__(256) void gemm_out(float* __restrict__ out,
                                                const float* __restrict__ bo) {
    gemm_core(g_c2, g_wo2, out, bo, 0);
}

// ==================== tcgen05 flash attention (P in TMEM, TS-mode O) =======
// TMEM (256): TS0 @0 | TS1 @64 | TO @128 | Ph @192 | Pl @224
#define ATT_IDESC 0x8100490u
#define AQ  1024
#define AK  (AQ + 32768)
#define AV  (AK + 16384)
#define ALS (AV + 16384)
#define ATT_SMEM 79872          // padded: cap at 2 CTAs/SM (TMEM limit)

__global__ __launch_bounds__(256, 2) void attn_tc() {
#if HAS_TCGEN05
    extern __shared__ char smem[];
    const uint32_t sb = smem_to_u32(smem);
    const int tid = threadIdx.x;
    const int wid = tid >> 5, lane = tid & 31;
    const int qt = 15 - blockIdx.x;
    const int bh = blockIdx.y;
    const int b  = bh >> 4, h = bh & 15;
    const int qbase = b * SEQ + qt * 128;
    const int colh  = h * HD;

    const uint32_t TMP = sb, MBS = sb + 8, MBO = sb + 16;

    if (wid == 0) { TCGEN05_ALLOC(TMP, 256); TCGEN05_RELINQUISH(); }
    if (tid == 0) { MBARRIER_INIT(MBS, 1); MBARRIER_INIT(MBO, 1); }
    __syncthreads();
    uint32_t tmem;
    asm volatile("ld.shared.b32 %0, [%1];" : "=r"(tmem) : "r"(TMP));
    const uint32_t TO = tmem + 128, PH = tmem + 192, PL = tmem + 224;

    const char* qs   = g_qimg + ((size_t)bh * 16 + qt) * 32768;
    const char* kimg = g_kimg + (size_t)bh * 32 * 16384;
    const char* vimg = g_vimg + (size_t)bh * 32 * 16384;

#pragma unroll
    for (int i = 0; i < 8; i++)
        *(uint4*)(smem + AQ + tid * 16 + i * 4096) =
            *(const uint4*)(qs + tid * 16 + i * 4096);
#pragma unroll
    for (int i = 0; i < 4; i++) {
        *(uint4*)(smem + AK + tid * 16 + i * 4096) =
            *(const uint4*)(kimg + tid * 16 + i * 4096);
        *(uint4*)(smem + AV + tid * 16 + i * 4096) =
            *(const uint4*)(vimg + tid * 16 + i * 4096);
    }
    FENCE_ASYNC();
    TCGEN05_FENCE_BEFORE();
    __syncthreads();

    const uint64_t qh = MAKE_SMEM_DESC(sb + AQ), ql = MAKE_SMEM_DESC(sb + AQ + 16384);
    const uint64_t kh = MAKE_SMEM_DESC(sb + AK), kl = MAKE_SMEM_DESC(sb + AK + 8192);
    const uint64_t vh = MAKE_SMEM_DESC(sb + AV), vl = MAKE_SMEM_DESC(sb + AV + 8192);

    if (wid == 0 && elect_one_pred()) {
        TCGEN05_FENCE_AFTER();
#pragma unroll
        for (int k = 0; k < 4; k++) mma_f16_ss(tmem, qh + k * 2, kh + k * 2, ATT_IDESC, k > 0);
#pragma unroll
        for (int k = 0; k < 4; k++) mma_f16_ss(tmem, ql + k * 2, kh + k * 2, ATT_IDESC, true);
#pragma unroll
        for (int k = 0; k < 4; k++) mma_f16_ss(tmem, qh + k * 2, kl + k * 2, ATT_IDESC, true);
        TCGEN05_COMMIT(MBS);
    }

    const int nkt = 2 * qt + 2;
    uint4 kreg[4], vreg[4];
#pragma unroll
    for (int j = 0; j < 4; j++)
        kreg[j] = *(const uint4*)(kimg + 16384 + tid * 16 + j * 4096);

    const int r_own = (wid & 3) * 32 + lane;
    const int cbh   = (wid >> 2) * 32;
    const uint32_t rowoff = (uint32_t)(wid & 3) << 21;
    const int qg    = qt * 128 + r_own;
    const int warp_min_qg = qt * 128 + (wid & 3) * 32;
    float l_part = 0.f;
    int phS = 0, phO = 0;

    for (int i = 0; i < nkt; i++) {
        const uint32_t TS_i = tmem + (i & 1) * 64;
        const uint32_t TS_n = tmem + ((i + 1) & 1) * 64;

        MBARRIER_WAIT_PARITY(MBS, phS & 1); phS++;
        TCGEN05_FENCE_AFTER();

        if (i + 1 < nkt) {
#pragma unroll
            for (int j = 0; j < 4; j++)
                *(uint4*)(smem + AK + tid * 16 + j * 4096) = kreg[j];
            FENCE_ASYNC();
            TCGEN05_FENCE_BEFORE();
        }
        __syncthreads();

        if (i + 1 < nkt && wid == 0 && elect_one_pred()) {
            TCGEN05_FENCE_AFTER();
#pragma unroll
            for (int k = 0; k < 4; k++) mma_f16_ss(TS_n, qh + k * 2, kh + k * 2, ATT_IDESC, k > 0);
#pragma unroll
            for (int k = 0; k < 4; k++) mma_f16_ss(TS_n, ql + k * 2, kh + k * 2, ATT_IDESC, true);
#pragma unroll
            for (int k = 0; k < 4; k++) mma_f16_ss(TS_n, qh + k * 2, kl + k * 2, ATT_IDESC, true);
            TCGEN05_COMMIT(MBS);
        }

        if (i + 2 < nkt) {
            const char* ks = kimg + (size_t)(i + 2) * 16384;
#pragma unroll
            for (int j = 0; j < 4; j++)
                kreg[j] = *(const uint4*)(ks + tid * 16 + j * 4096);
        }

        // wait O(i-1): frees V smem AND Ph/Pl TMEM for overwrite
        if (i > 0) {
            MBARRIER_WAIT_PARITY(MBO, phO & 1); phO++;
            TCGEN05_FENCE_AFTER();
#pragma unroll
            for (int j = 0; j < 4; j++)
                *(uint4*)(smem + AV + tid * 16 + j * 4096) = vreg[j];
        }

        // ---- softmax: single LDTM x32 -> exp -> split -> 4x STTM x8 ----
        {
            uint32_t sr[32];
            TCGEN05_LD_X32(sr, TS_i + cbh);
            TCGEN05_WAIT_LD();
            const bool nomask = (i * 64 + cbh + 31) <= warp_min_qg;
            uint32_t php[16], plp[16];
            if (nomask) {
#pragma unroll
                for (int c = 0; c < 16; c++) {
                    float p0 = ex2f(__uint_as_float(sr[2 * c]));
                    float p1 = ex2f(__uint_as_float(sr[2 * c + 1]));
                    l_part += p0 + p1;
                    __nv_bfloat16 hb[2], lb[2];
                    hb[0] = __float2bfloat16_rn(p0);
                    hb[1] = __float2bfloat16_rn(p1);
                    lb[0] = __float2bfloat16_rn(p0 - __bfloat162float(hb[0]));
                    lb[1] = __float2bfloat16_rn(p1 - __bfloat162float(hb[1]));
                    php[c] = *(uint32_t*)hb;
                    plp[c] = *(uint32_t*)lb;
                }
            } else {
#pragma unroll
                for (int c = 0; c < 16; c++) {
                    int j0 = i * 64 + cbh + 2 * c;
                    float p0 = (j0     <= qg) ? ex2f(__uint_as_float(sr[2 * c]))     : 0.f;
                    float p1 = (j0 + 1 <= qg) ? ex2f(__uint_as_float(sr[2 * c + 1])) : 0.f;
                    l_part += p0 + p1;
                    __nv_bfloat16 hb[2], lb[2];
                    hb[0] = __float2bfloat16_rn(p0);
                    hb[1] = __float2bfloat16_rn(p1);
                    lb[0] = __float2bfloat16_rn(p0 - __bfloat162float(hb[0]));
                    lb[1] = __float2bfloat16_rn(p1 - __bfloat162float(hb[1]));
                    php[c] = *(uint32_t*)hb;
                    plp[c] = *(uint32_t*)lb;
                }
            }
            TCGEN05_ST_X8(PH + (cbh >> 1) + rowoff,     php);
            TCGEN05_ST_X8(PH + (cbh >> 1) + 8 + rowoff, php + 8);
            TCGEN05_ST_X8(PL + (cbh >> 1) + rowoff,     plp);
            TCGEN05_ST_X8(PL + (cbh >> 1) + 8 + rowoff, plp + 8);
        }
        TCGEN05_WAIT_ST();
        FENCE_ASYNC();             // V store visibility
        TCGEN05_FENCE_BEFORE();
        __syncthreads();           // all warps' STTM + V stores done

        // ---- O(i) += Ph*Vh + Pl*Vh + Ph*Vl  (TS mode: A from TMEM) ----
        if (wid == 0 && elect_one_pred()) {
            TCGEN05_FENCE_AFTER();
#pragma unroll
            for (int k = 0; k < 4; k++)
                mma_f16_ts(TO, PH + k * 8, vh + k * 2, ATT_IDESC, !(i == 0 && k == 0));
#pragma unroll
            for (int k = 0; k < 4; k++)
                mma_f16_ts(TO, PL + k * 8, vh + k * 2, ATT_IDESC, true);
#pragma unroll
            for (int k = 0; k < 4; k++)
                mma_f16_ts(TO, PH + k * 8, vl + k * 2, ATT_IDESC, true);
            TCGEN05_COMMIT(MBO);
        }
        if (i + 1 < nkt) {
            const char* vs = vimg + (size_t)(i + 1) * 16384;
#pragma unroll
            for (int j = 0; j < 4; j++)
                vreg[j] = *(const uint4*)(vs + tid * 16 + j * 4096);
        }
    }

    // ---- epilogue: O/l with fused [hi|lo] split store to g_c2 ----
    MBARRIER_WAIT_PARITY(MBO, phO & 1); phO++;
    TCGEN05_FENCE_AFTER();

    float* l_sh = (float*)(smem + ALS);
    l_sh[r_own * 2 + (wid >> 2)] = l_part;
    __syncthreads();
    float linv = 1.f / (l_sh[r_own * 2] + l_sh[r_own * 2 + 1]);

    uint32_t orr[32];
    TCGEN05_LD_X32(orr, TO + cbh);
    TCGEN05_WAIT_LD();
    TCGEN05_FENCE_BEFORE();

    __nv_bfloat16* base = g_c2 + (size_t)(qbase + r_own) * DK2 + colh + cbh;
#pragma unroll
    for (int c = 0; c < 32; c += 4) {
        float f[4];
        __nv_bfloat16 hh[4], ll[4];
#pragma unroll
        for (int e = 0; e < 4; e++) {
            f[e] = __uint_as_float(orr[c + e]) * linv;
            hh[e] = __float2bfloat16_rn(f[e]);
            ll[e] = __float2bfloat16_rn(f[e] - __bfloat162float(hh[e]));
        }
        *(uint2*)(base + c)        = *(uint2*)hh;
        *(uint2*)(base + 1024 + c) = *(uint2*)ll;
    }
    __syncthreads();
    if (tid == 0) { MBARRIER_INVAL(MBS); MBARRIER_INVAL(MBO); }
    __syncthreads();
    if (wid == 0) TCGEN05_DEALLOC(tmem, 256);
#else
    const int qt = 15 - blockIdx.x, bh = blockIdx.y;
    const int b = bh >> 4, h = bh & 15;
    const int r = threadIdx.x >> 1;
    const int d0 = (threadIdx.x & 1) * 32;
    const int qrow = b * SEQ + qt * 128 + r;
    const int qg = qt * 128 + r;
    const float* qp = g_q + (size_t)qrow * DIN + h * HD;
    float o[32];
#pragma unroll
    for (int dd = 0; dd < 32; dd++) o[dd] = 0.f;
    float l = 0.f;
    for (int j = 0; j <= qg; j++) {
        const float* kp = g_k + (size_t)(b * SEQ + j) * DIN + h * HD;
        float s = 0.f;
        for (int d = 0; d < 64; d++) s += qp[d] * kp[d];
        float p = exp2f(s);
        l += p;
        const float* vp = g_v + (size_t)(b * SEQ + j) * DIN + h * HD + d0;
        for (int dd = 0; dd < 32; dd++) o[dd] += p * vp[dd];
    }
    __nv_bfloat16* base = g_c2 + (size_t)qrow * DK2 + h * HD + d0;
    for (int dd = 0; dd < 32; dd++) {
        float f = o[dd] / l;
        __nv_bfloat16 hh = __float2bfloat16_rn(f);
        __nv_bfloat16 ll = __float2bfloat16_rn(f - __bfloat162float(hh));
        base[dd] = hh;
        base[1024 + dd] = ll;
    }
#endif
}

// ==================== launch ====================
extern "C" void kernel_launch(void* const* d_in, const int* in_sizes, int n_in,
                              void* d_out, int out_size) {
    const float* x  = (const float*)d_in[0];
    const float* Wq = (const float*)d_in[1];
    const float* Wk = (const float*)d_in[2];
    const float* Wv = (const float*)d_in[3];
    const float* Wo = (const float*)d_in[4];
    const float* bo = (const float*)d_in[5];
    float* out = (float*)d_out;

    cudaFuncSetAttribute(attn_tc, cudaFuncAttributeMaxDynamicSharedMemorySize, ATT_SMEM);
    cudaFuncSetAttribute(gemm_qkv, cudaFuncAttributeMaxDynamicSharedMemorySize, GEMM_SMEM);
    cudaFuncSetAttribute(gemm_out, cudaFuncAttributeMaxDynamicSharedMemorySize, GEMM_SMEM);

    split_all<<<12288, 256>>>(x, Wq, Wk, Wv, Wo);
    gemm_qkv<<<dim3(4, 32, 3), 256, GEMM_SMEM>>>();
    attn_tc<<<dim3(16, 64), 256, ATT_SMEM>>>();
    gemm_out<<<dim3(4, 32), 256, GEMM_SMEM>>>(out, bo);
}

// round 16
// speedup vs baseline: 1.2478x; 1.0361x over previous
#include <cuda_runtime.h>
#include <cuda_bf16.h>
#include <cstdint>

#define DIN  1024
#define DK2  2048      // [hi | lo] dedup split-K
#define DM   8192      // B*S
#define NH   16
#define HD   64
#define SEQ  2048
#define QSCALE 0.18033688011112042f   // 0.125 * log2(e)

#if defined(__CUDA_ARCH_FEAT_SM103_ALL) || defined(__CUDA_ARCH_FEAT_SM100_ALL)
#define HAS_TCGEN05 1
#else
#define HAS_TCGEN05 0
#endif

// ---------------- scratch (device globals: allocation-free) ----------------
__device__ float g_q[DM * DIN];              // fallback path only
__device__ float g_k[DM * DIN];
__device__ float g_v[DM * DIN];
__device__ __nv_bfloat16 g_x2[DM * DK2];     // [hi | lo]
__device__ __nv_bfloat16 g_c2[DM * DK2];     // ctx split (attn epilogue writes)
__device__ __nv_bfloat16 g_wq2[DIN * DK2];
__device__ __nv_bfloat16 g_wk2[DIN * DK2];
__device__ __nv_bfloat16 g_wv2[DIN * DK2];
__device__ __nv_bfloat16 g_wo2[DIN * DK2];
__device__ char g_kimg[64u * 32u * 16384u];
__device__ char g_vimg[64u * 32u * 16384u];
__device__ char g_qimg[64u * 16u * 32768u];

// ==================== helpers ====================
__device__ __forceinline__ uint32_t smem_to_u32(const void* p) {
    uint32_t a;
    asm("{ .reg .u64 t; cvta.to.shared.u64 t, %1; cvt.u32.u64 %0, t; }" : "=r"(a) : "l"(p));
    return a;
}
#define SMEM_SWIZZLE_128B(o) ((o) ^ (((o) >> 3) & 0x70))

__device__ __forceinline__ float ex2f(float x) {
    float r;
    asm("ex2.approx.f32 %0, %1;" : "=f"(r) : "f"(x));
    return r;
}
// truncation split: hi = top16(f) packed via PRMT; lo = rn(f - hi)
__device__ __forceinline__ void split_pair_trunc(float f0, float f1,
                                                 uint32_t &hi_pair, uint32_t &lo_pair) {
    uint32_t u0 = __float_as_uint(f0), u1 = __float_as_uint(f1);
    asm("prmt.b32 %0, %1, %2, 0x7632;" : "=r"(hi_pair) : "r"(u0), "r"(u1));
    float h0 = __uint_as_float(u0 & 0xFFFF0000u);
    float h1 = __uint_as_float(u1 & 0xFFFF0000u);
    float l0 = f0 - h0, l1 = f1 - h1;
    asm("cvt.rn.bf16x2.f32 %0, %1, %2;" : "=r"(lo_pair) : "f"(l1), "f"(l0));
}

#if HAS_TCGEN05
__device__ __forceinline__ uint32_t elect_one_pred() {
    uint32_t pred;
    asm volatile("{\n\t.reg .pred p;\n\telect.sync _|p, 0xFFFFFFFF;\n\t"
                 "selp.b32 %0, 1, 0, p;\n\t}" : "=r"(pred));
    return pred;
}

static constexpr uint64_t SMEM_DESC_BASE_SW128 =
    (uint64_t(2) << 61) | (uint64_t(1) << 46) | (uint64_t(64) << 32) | (uint64_t(1) << 16);
#define MAKE_SMEM_DESC(a) (SMEM_DESC_BASE_SW128 | ((uint64_t)((a) >> 4) & 0x3FFF))

#define TCGEN05_ALLOC(sr, n) \
    asm volatile("tcgen05.alloc.cta_group::1.sync.aligned.shared::cta.b32 [%0], %1;" \
                 :: "r"((uint32_t)(sr)), "r"((uint32_t)(n)) : "memory")
#define TCGEN05_DEALLOC(t, n) \
    asm volatile("tcgen05.dealloc.cta_group::1.sync.aligned.b32 %0, %1;" :: "r"(t), "r"((uint32_t)(n)))
#define TCGEN05_RELINQUISH() \
    asm volatile("tcgen05.relinquish_alloc_permit.cta_group::1.sync.aligned;")
#define TCGEN05_COMMIT(mb) \
    asm volatile("tcgen05.commit.cta_group::1.mbarrier::arrive::one.shared::cluster.b64 [%0];" \
                 :: "r"((uint32_t)(mb)) : "memory")
#define TCGEN05_WAIT_LD()  asm volatile("tcgen05.wait::ld.sync.aligned;" ::: "memory")
#define TCGEN05_WAIT_ST()  asm volatile("tcgen05.wait::st.sync.aligned;" ::: "memory")
#define TCGEN05_FENCE_BEFORE() asm volatile("tcgen05.fence::before_thread_sync;" ::: "memory")
#define TCGEN05_FENCE_AFTER()  asm volatile("tcgen05.fence::after_thread_sync;" ::: "memory")
#define FENCE_ASYNC() asm volatile("fence.proxy.async.shared::cta;" ::: "memory")

#define CP_ASYNC16(dst, src) \
    asm volatile("cp.async.cg.shared.global [%0], [%1], 16;" \
                 :: "r"((uint32_t)(dst)), "l"(src) : "memory")
#define CP_COMMIT() asm volatile("cp.async.commit_group;" ::: "memory")
#define CP_WAIT(n)  asm volatile("cp.async.wait_group %0;" :: "n"(n) : "memory")

#define MBARRIER_INIT(mb, c) \
    asm volatile("mbarrier.init.shared.b64 [%0], %1;" :: "r"((uint32_t)(mb)), "r"((uint32_t)(c)) : "memory")
#define MBARRIER_INVAL(mb) \
    asm volatile("mbarrier.inval.shared.b64 [%0];" :: "r"((uint32_t)(mb)) : "memory")
#define MBARRIER_WAIT_PARITY(mb, ph) do { \
    uint32_t _mb = (uint32_t)(mb), _p = (uint32_t)(ph), _d; \
    asm volatile("{\n\t.reg .pred p;\n\t" \
        "mbarrier.try_wait.parity.acquire.cta.shared::cta.b64 p, [%1], %2;\n\t" \
        "selp.b32 %0, 1, 0, p;\n\t}" : "=r"(_d) : "r"(_mb), "r"(_p) : "memory"); \
    if (!_d) { \
        asm volatile("{\n\t.reg .pred P1;\n\tWL_%=:\n\t" \
            "mbarrier.try_wait.parity.acquire.cta.shared::cta.b64 P1, [%0], %1, 0x989680;\n\t" \
            "@P1 bra.uni WD_%=;\n\tbra.uni WL_%=;\n\tWD_%=:\n\t}" \
            :: "r"(_mb), "r"(_p) : "memory"); \
    } } while (0)

#define TCGEN05_LD_X32(r, a) \
    asm volatile("tcgen05.ld.sync.aligned.32x32b.x32.b32 " \
        "{%0,%1,%2,%3,%4,%5,%6,%7,%8,%9,%10,%11,%12,%13,%14,%15," \
        "%16,%17,%18,%19,%20,%21,%22,%23,%24,%25,%26,%27,%28,%29,%30,%31}, [%32];" \
        : "=r"((r)[0]),"=r"((r)[1]),"=r"((r)[2]),"=r"((r)[3]),"=r"((r)[4]),"=r"((r)[5]), \
          "=r"((r)[6]),"=r"((r)[7]),"=r"((r)[8]),"=r"((r)[9]),"=r"((r)[10]),"=r"((r)[11]), \
          "=r"((r)[12]),"=r"((r)[13]),"=r"((r)[14]),"=r"((r)[15]),"=r"((r)[16]),"=r"((r)[17]), \
          "=r"((r)[18]),"=r"((r)[19]),"=r"((r)[20]),"=r"((r)[21]),"=r"((r)[22]),"=r"((r)[23]), \
          "=r"((r)[24]),"=r"((r)[25]),"=r"((r)[26]),"=r"((r)[27]),"=r"((r)[28]),"=r"((r)[29]), \
          "=r"((r)[30]),"=r"((r)[31]) : "r"(a))

#define TCGEN05_ST_X8(a, r) \
    asm volatile("tcgen05.st.sync.aligned.32x32b.x8.b32 [%0], " \
        "{%1,%2,%3,%4,%5,%6,%7,%8};" \
        :: "r"(a), "r"((r)[0]), "r"((r)[1]), "r"((r)[2]), "r"((r)[3]), \
           "r"((r)[4]), "r"((r)[5]), "r"((r)[6]), "r"((r)[7]) : "memory")

__device__ __forceinline__ void mma_f16_ss(uint32_t d, uint64_t a, uint64_t b,
                                           uint32_t idesc, bool acc) {
    uint32_t en = acc ? 1u : 0u;
    asm volatile("{\n\t.reg .pred p;\n\tsetp.ne.u32 p, %5, 0;\n\t"
                 "tcgen05.mma.cta_group::1.kind::f16 [%0], %1, %2, %3, {%4,%4,%4,%4}, p;\n\t}"
                 :: "r"(d), "l"(a), "l"(b), "r"(idesc), "r"(0u), "r"(en) : "memory");
}
__device__ __forceinline__ void mma_f16_ts(uint32_t d, uint32_t a_tmem, uint64_t b,
                                           uint32_t idesc, bool acc) {
    uint32_t en = acc ? 1u : 0u;
    asm volatile("{\n\t.reg .pred p;\n\tsetp.ne.u32 p, %5, 0;\n\t"
                 "tcgen05.mma.cta_group::1.kind::f16 [%0], [%1], %2, %3, {%4,%4,%4,%4}, p;\n\t}"
                 :: "r"(d), "r"(a_tmem), "l"(b), "r"(idesc), "r"(0u), "r"(en) : "memory");
}
#endif  // HAS_TCGEN05

// ==================== fp32 -> [hi|lo] bf16 split (merged x + weights) ======
__global__ __launch_bounds__(256) void split_all(const float* __restrict__ x,
                                                 const float* __restrict__ Wq,
                                                 const float* __restrict__ Wk,
                                                 const float* __restrict__ Wv,
                                                 const float* __restrict__ Wo) {
    const float* src; __nv_bfloat16* dst; size_t blk;
    if (blockIdx.x < 8192) { src = x; dst = g_x2; blk = blockIdx.x; }
    else {
        int w = (blockIdx.x - 8192) >> 10;
        blk = (blockIdx.x - 8192) & 1023;
        switch (w) {
            case 0: src = Wq; dst = g_wq2; break;
            case 1: src = Wk; dst = g_wk2; break;
            case 2: src = Wv; dst = g_wv2; break;
            default: src = Wo; dst = g_wo2; break;
        }
    }
    size_t i = (blk * 256 + threadIdx.x) * 4;
    size_t row = i >> 10;
    int    col = (int)(i & 1023);
    float4 v = *(const float4*)(src + i);
    float f[4] = {v.x, v.y, v.z, v.w};
    __nv_bfloat16 h[4], l[4];
#pragma unroll
    for (int j = 0; j < 4; j++) {
        h[j] = __float2bfloat16_rn(f[j]);
        l[j] = __float2bfloat16_rn(f[j] - __bfloat162float(h[j]));
    }
    __nv_bfloat16* base = dst + row * DK2 + col;
    *(uint2*)(base)        = *(uint2*)h;
    *(uint2*)(base + 1024) = *(uint2*)l;
}

// ==================== tcgen05 projection GEMM: 256x256 tile, TMEM 512 ======
#define GEMM_CHUNKS 16
#define A_OFF0 1024
#define A_OFF1 (1024 + 32768)
#define B_OFF  (1024 + 65536)
#define GEMM_SMEM (1024 + 65536 + 131072)   // 197632
#define GEMM_IDESC 0x8400490u

__device__ __forceinline__ void gemm_core(const __nv_bfloat16* __restrict__ A,
                                          const __nv_bfloat16* __restrict__ B,
                                          float* __restrict__ C,
                                          const float* __restrict__ bias,
                                          int mode) {
#if HAS_TCGEN05
    extern __shared__ char smem[];
    const uint32_t sb = smem_to_u32(smem);
    const int tid = threadIdx.x, wid = tid >> 5, lid = tid & 31;
    const int bm = blockIdx.y * 256;
    const int bn = blockIdx.x * 256;

    const uint32_t TM_PTR = sb, MBH0 = sb + 8, MBH1 = sb + 16;

    if (wid == 0) { TCGEN05_ALLOC(TM_PTR, 512); TCGEN05_RELINQUISH(); }
    if (tid == 0) { MBARRIER_INIT(MBH0, 1); MBARRIER_INIT(MBH1, 1); }
    __syncthreads();
    uint32_t tmem;
    asm volatile("ld.shared.b32 %0, [%1];" : "=r"(tmem) : "r"(TM_PTR));

    auto issue_A = [&](int half, int c) {
        const uint32_t ab = sb + (half ? A_OFF1 : A_OFF0);
        const __nv_bfloat16* Ap = A + (size_t)(bm + half * 128) * DK2 + c * 64;
#pragma unroll
        for (int i = 0; i < 4; i++) {
            int lin = tid + i * 256;
            int row = lin >> 3, q = lin & 7;
            uint32_t sw = SMEM_SWIZZLE_128B(row * 128 + q * 16);
            CP_ASYNC16(ab + sw,         Ap + (size_t)row * DK2 + q * 8);
            CP_ASYNC16(ab + 16384 + sw, Ap + (size_t)row * DK2 + 1024 + q * 8);
        }
    };
    auto issue_B = [&](int c) {
        const uint32_t bb = sb + B_OFF + (c & 1) * 65536;
        const __nv_bfloat16* Bp = B + (size_t)bn * DK2 + c * 64;
#pragma unroll
        for (int i = 0; i < 8; i++) {
            int lin = tid + i * 256;
            int row = lin >> 3, q = lin & 7;
            uint32_t sw = SMEM_SWIZZLE_128B(row * 128 + q * 16);
            CP_ASYNC16(bb + sw,         Bp + (size_t)row * DK2 + q * 8);
            CP_ASYNC16(bb + 32768 + sw, Bp + (size_t)row * DK2 + 1024 + q * 8);
        }
    };
    auto issue_mma = [&](int half, int c) {
        const uint32_t ab = sb + (half ? A_OFF1 : A_OFF0);
        const uint32_t bb = sb + B_OFF + (c & 1) * 65536;
        uint64_t ah = MAKE_SMEM_DESC(ab), al = MAKE_SMEM_DESC(ab + 16384);
        uint64_t bh = MAKE_SMEM_DESC(bb), bl = MAKE_SMEM_DESC(bb + 32768);
        const uint32_t D = tmem + half * 256;
#pragma unroll
        for (int k = 0; k < 4; k++)
            mma_f16_ss(D, ah + k * 2, bh + k * 2, GEMM_IDESC, !(c == 0 && k == 0));
#pragma unroll
        for (int k = 0; k < 4; k++)
            mma_f16_ss(D, al + k * 2, bh + k * 2, GEMM_IDESC, true);
#pragma unroll
        for (int k = 0; k < 4; k++)
            mma_f16_ss(D, ah + k * 2, bl + k * 2, GEMM_IDESC, true);
    };

    issue_A(0, 0); CP_COMMIT();
    issue_B(0);    CP_COMMIT();
    issue_A(1, 0); CP_COMMIT();
    issue_B(1);    CP_COMMIT();

    int ph0 = 0, ph1 = 0;
    for (int c = 0; c < GEMM_CHUNKS; c++) {
        if (c >= 1) {
            MBARRIER_WAIT_PARITY(MBH1, ph1 & 1); ph1++;
            issue_A(1, c); CP_COMMIT();
            if (c + 1 < GEMM_CHUNKS) issue_B(c + 1);
            CP_COMMIT();
        }
        CP_WAIT(2);
        FENCE_ASYNC();
        TCGEN05_FENCE_BEFORE();
        __syncthreads();
        if (wid == 0 && elect_one_pred()) {
            TCGEN05_FENCE_AFTER();
            issue_mma(0, c);
            TCGEN05_COMMIT(MBH0);
        }
        CP_WAIT(1);
        FENCE_ASYNC();
        TCGEN05_FENCE_BEFORE();
        __syncthreads();
        if (wid == 0 && elect_one_pred()) {
            TCGEN05_FENCE_AFTER();
            issue_mma(1, c);
            TCGEN05_COMMIT(MBH1);
        }
        MBARRIER_WAIT_PARITY(MBH0, ph0 & 1); ph0++;
        if (c + 1 < GEMM_CHUNKS) issue_A(0, c + 1);
        CP_COMMIT();
    }
    MBARRIER_WAIT_PARITY(MBH1, ph1 & 1); ph1++;
    TCGEN05_FENCE_AFTER();

    for (int half = 0; half < 2; half++) {
        const uint32_t D = tmem + half * 256;
        const int bmh = bm + half * 128;
        if (mode == 0) {
            if (wid < 4) {
                const int row = bmh + wid * 32 + lid;
                float* Crow = C + (size_t)row * DIN + bn;
#pragma unroll
                for (int cb = 0; cb < 256; cb += 32) {
                    uint32_t r[32];
                    TCGEN05_LD_X32(r, D + cb);
                    TCGEN05_WAIT_LD();
#pragma unroll
                    for (int j = 0; j < 32; j += 4) {
                        float4 v;
                        v.x = __uint_as_float(r[j + 0]) + bias[bn + cb + j + 0];
                        v.y = __uint_as_float(r[j + 1]) + bias[bn + cb + j + 1];
                        v.z = __uint_as_float(r[j + 2]) + bias[bn + cb + j + 2];
                        v.w = __uint_as_float(r[j + 3]) + bias[bn + cb + j + 3];
                        *(float4*)(Crow + cb + j) = v;
                    }
                }
                TCGEN05_FENCE_BEFORE();
            }
        } else {
            char* stg = smem + 1024;
            if (wid < 4) {
                const int rl = wid * 32 + lid;
                const int ktl = rl >> 6, rk = rl & 63;
#pragma unroll
                for (int cb = 0; cb < 256; cb += 32) {
                    uint32_t r[32];
                    TCGEN05_LD_X32(r, D + cb);
                    TCGEN05_WAIT_LD();
                    const int head = cb >> 6;
                    const int hd0  = cb & 63;
                    if (mode == 1) {
                        char* base = stg + head * 32768;
#pragma unroll
                        for (int c = 0; c < 32; c += 2) {
                            float f0 = __uint_as_float(r[c])     * QSCALE;
                            float f1 = __uint_as_float(r[c + 1]) * QSCALE;
                            __nv_bfloat16 hb[2], lb[2];
                            hb[0] = __float2bfloat16_rn(f0);
                            hb[1] = __float2bfloat16_rn(f1);
                            lb[0] = __float2bfloat16_rn(f0 - __bfloat162float(hb[0]));
                            lb[1] = __float2bfloat16_rn(f1 - __bfloat162float(hb[1]));
                            uint32_t off = SMEM_SWIZZLE_128B(rl * 128 + (hd0 + c) * 2);
                            *(uint32_t*)(base + off)         = *(uint32_t*)hb;
                            *(uint32_t*)(base + 16384 + off) = *(uint32_t*)lb;
                        }
                    } else if (mode == 2) {
                        char* base = stg + (head * 2 + ktl) * 16384;
#pragma unroll
                        for (int c = 0; c < 32; c += 2) {
                            float f0 = __uint_as_float(r[c]);
                            float f1 = __uint_as_float(r[c + 1]);
                            __nv_bfloat16 hb[2], lb[2];
                            hb[0] = __float2bfloat16_rn(f0);
                            hb[1] = __float2bfloat16_rn(f1);
                            lb[0] = __float2bfloat16_rn(f0 - __bfloat162float(hb[0]));
                            lb[1] = __float2bfloat16_rn(f1 - __bfloat162float(hb[1]));
                            uint32_t off = SMEM_SWIZZLE_128B(rk * 128 + (hd0 + c) * 2);
                            *(uint32_t*)(base + off)        = *(uint32_t*)hb;
                            *(uint32_t*)(base + 8192 + off) = *(uint32_t*)lb;
                        }
                    } else {
                        char* base = stg + (head * 2 + ktl) * 16384;
#pragma unroll
                        for (int c = 0; c < 32; c++) {
                            float f = __uint_as_float(r[c]);
                            __nv_bfloat16 vh = __float2bfloat16_rn(f);
                            __nv_bfloat16 vl = __float2bfloat16_rn(f - __bfloat162float(vh));
                            uint32_t toff = SMEM_SWIZZLE_128B((hd0 + c) * 128 + rk * 2);
                            *(__nv_bfloat16*)(base + toff)        = vh;
                            *(__nv_bfloat16*)(base + 8192 + toff) = vl;
                        }
                    }
                }
                TCGEN05_FENCE_BEFORE();
            }
            __syncthreads();
            const int bb = bmh >> 11;
            const int h0 = bn >> 6;
            if (mode == 1) {
                const int qt = (bmh & 2047) >> 7;
#pragma unroll
                for (int hh = 0; hh < 4; hh++) {
                    char* dst = g_qimg + (((size_t)(bb * 16 + h0 + hh)) * 16 + qt) * 32768;
                    const char* src = stg + hh * 32768;
#pragma unroll
                    for (int i2 = 0; i2 < 8; i2++)
                        *(uint4*)(dst + tid * 16 + i2 * 4096) =
                            *(const uint4*)(src + tid * 16 + i2 * 4096);
                }
            } else {
                const int kt0 = (bmh & 2047) >> 6;
                char* gimg = (mode == 2) ? g_kimg : g_vimg;
#pragma unroll
                for (int im = 0; im < 8; im++) {
                    int hh = im >> 1, kk = im & 1;
                    char* dst = gimg + (((size_t)(bb * 16 + h0 + hh)) * 32 + kt0 + kk) * 16384;
                    const char* src = stg + im * 16384;
#pragma unroll
                    for (int i2 = 0; i2 < 4; i2++)
                        *(uint4*)(dst + tid * 16 + i2 * 4096) =
                            *(const uint4*)(src + tid * 16 + i2 * 4096);
                }
            }
            __syncthreads();
        }
    }
    __syncthreads();
    if (tid == 0) { MBARRIER_INVAL(MBH0); MBARRIER_INVAL(MBH1); }
    __syncthreads();
    if (wid == 0) TCGEN05_DEALLOC(tmem, 512);
#else
    extern __shared__ char smem[];
    __nv_bfloat16* Achunk = (__nv_bfloat16*)(smem);
    const int tid = threadIdx.x;
    const int bn = blockIdx.x * 256;
    for (int half = 0; half < 2; half++) {
        const int bm = blockIdx.y * 256 + half * 128;
        float acc[128];
        const int nt = tid;
#pragma unroll
        for (int i = 0; i < 128; i++) acc[i] = 0.f;
        for (int c = 0; c < GEMM_CHUNKS; c++) {
            for (int i = tid; i < 128 * 128 / 8; i += 256) {
                int row = i / 16, q = (i % 16) * 8;
                int col = (q < 64) ? (c * 64 + q) : (1024 + c * 64 + q - 64);
                *(uint4*)&Achunk[row * 128 + q] =
                    *(const uint4*)(A + (size_t)(bm + row) * DK2 + col);
            }
            __syncthreads();
            const __nv_bfloat16* Bp = B + (size_t)(bn + nt) * DK2 + c * 64;
            for (int k = 0; k < 64; k++) {
                float bh = __bfloat162float(Bp[k]);
                float bl = __bfloat162float(Bp[1024 + k]);
                for (int m = 0; m < 128; m++) {
                    float ah = __bfloat162float(Achunk[m * 128 + k]);
                    float al = __bfloat162float(Achunk[m * 128 + 64 + k]);
                    acc[m] += ah * bh + al * bh + ah * bl;
                }
            }
            __syncthreads();
        }
        float bbv = (mode == 0) ? bias[bn + nt] : 0.f;
        float sc  = (mode == 1) ? QSCALE : 1.f;
        for (int m = 0; m < 128; m++)
            C[(size_t)(bm + m) * DIN + bn + nt] = acc[m] * sc + bbv;
        __syncthreads();
    }
#endif
}

__global__ __launch_bounds__(256) void gemm_qkv() {
    const __nv_bfloat16* B; float* C; int mode;
    if (blockIdx.z == 0)      { B = g_wq2; C = g_q; mode = 1; }
    else if (blockIdx.z == 1) { B = g_wk2; C = g_k; mode = 2; }
    else                      { B = g_wv2; C = g_v; mode = 3; }
    gemm_core(g_x2, B, C, nullptr, mode);
}
__global__ __launch_bounds__(256) void gemm_out(float* __restrict__ out,
                                                const float* __restrict__ bo) {
    gemm_core(g_c2, g_wo2, out, bo, 0);
}

// ==================== tcgen05 flash attention (P in TMEM, TS-mode O) =======
// TMEM (256): TS0 @0 | TS1 @64 | TO @128 | Ph @192 | Pl @224
#define ATT_IDESC 0x8100490u
#define AQ  1024
#define AK  (AQ + 32768)
#define AV  (AK + 16384)
#define ALS (AV + 16384)
#define ATT_SMEM 79872          // padded: cap at 2 CTAs/SM (TMEM limit)

__global__ __launch_bounds__(256, 2) void attn_tc() {
#if HAS_TCGEN05
    extern __shared__ char smem[];
    const uint32_t sb = smem_to_u32(smem);
    const int tid = threadIdx.x;
    const int wid = tid >> 5, lane = tid & 31;
    const int qt = 15 - blockIdx.x;
    const int bh = blockIdx.y;
    const int b  = bh >> 4, h = bh & 15;
    const int qbase = b * SEQ + qt * 128;
    const int colh  = h * HD;

    const uint32_t TMP = sb, MBS = sb + 8, MBO = sb + 16;

    if (wid == 0) { TCGEN05_ALLOC(TMP, 256); TCGEN05_RELINQUISH(); }
    if (tid == 0) { MBARRIER_INIT(MBS, 1); MBARRIER_INIT(MBO, 1); }
    __syncthreads();
    uint32_t tmem;
    asm volatile("ld.shared.b32 %0, [%1];" : "=r"(tmem) : "r"(TMP));
    const uint32_t TO = tmem + 128, PH = tmem + 192, PL = tmem + 224;

    const char* qs   = g_qimg + ((size_t)bh * 16 + qt) * 32768;
    const char* kimg = g_kimg + (size_t)bh * 32 * 16384;
    const char* vimg = g_vimg + (size_t)bh * 32 * 16384;

#pragma unroll
    for (int i = 0; i < 8; i++)
        *(uint4*)(smem + AQ + tid * 16 + i * 4096) =
            *(const uint4*)(qs + tid * 16 + i * 4096);
#pragma unroll
    for (int i = 0; i < 4; i++) {
        *(uint4*)(smem + AK + tid * 16 + i * 4096) =
            *(const uint4*)(kimg + tid * 16 + i * 4096);
        *(uint4*)(smem + AV + tid * 16 + i * 4096) =
            *(const uint4*)(vimg + tid * 16 + i * 4096);
    }
    FENCE_ASYNC();
    TCGEN05_FENCE_BEFORE();
    __syncthreads();

    const uint64_t qh = MAKE_SMEM_DESC(sb + AQ), ql = MAKE_SMEM_DESC(sb + AQ + 16384);
    const uint64_t kh = MAKE_SMEM_DESC(sb + AK), kl = MAKE_SMEM_DESC(sb + AK + 8192);
    const uint64_t vh = MAKE_SMEM_DESC(sb + AV), vl = MAKE_SMEM_DESC(sb + AV + 8192);

    if (wid == 0 && elect_one_pred()) {
        TCGEN05_FENCE_AFTER();
#pragma unroll
        for (int k = 0; k < 4; k++) mma_f16_ss(tmem, qh + k * 2, kh + k * 2, ATT_IDESC, k > 0);
#pragma unroll
        for (int k = 0; k < 4; k++) mma_f16_ss(tmem, ql + k * 2, kh + k * 2, ATT_IDESC, true);
#pragma unroll
        for (int k = 0; k < 4; k++) mma_f16_ss(tmem, qh + k * 2, kl + k * 2, ATT_IDESC, true);
        TCGEN05_COMMIT(MBS);
    }

    const int nkt = 2 * qt + 2;
    uint4 kreg[4], vreg[4];
#pragma unroll
    for (int j = 0; j < 4; j++)
        kreg[j] = *(const uint4*)(kimg + 16384 + tid * 16 + j * 4096);

    const int r_own = (wid & 3) * 32 + lane;
    const int cbh   = (wid >> 2) * 32;
    const uint32_t rowoff = (uint32_t)(wid & 3) << 21;
    const int qg    = qt * 128 + r_own;
    const int warp_min_qg = qt * 128 + (wid & 3) * 32;
    float l_part = 0.f;
    int phS = 0, phO = 0;

    for (int i = 0; i < nkt; i++) {
        const uint32_t TS_i = tmem + (i & 1) * 64;
        const uint32_t TS_n = tmem + ((i + 1) & 1) * 64;

        MBARRIER_WAIT_PARITY(MBS, phS & 1); phS++;
        TCGEN05_FENCE_AFTER();

        if (i + 1 < nkt) {
#pragma unroll
            for (int j = 0; j < 4; j++)
                *(uint4*)(smem + AK + tid * 16 + j * 4096) = kreg[j];
            FENCE_ASYNC();
            TCGEN05_FENCE_BEFORE();
        }
        __syncthreads();

        if (i + 1 < nkt && wid == 0 && elect_one_pred()) {
            TCGEN05_FENCE_AFTER();
#pragma unroll
            for (int k = 0; k < 4; k++) mma_f16_ss(TS_n, qh + k * 2, kh + k * 2, ATT_IDESC, k > 0);
#pragma unroll
            for (int k = 0; k < 4; k++) mma_f16_ss(TS_n, ql + k * 2, kh + k * 2, ATT_IDESC, true);
#pragma unroll
            for (int k = 0; k < 4; k++) mma_f16_ss(TS_n, qh + k * 2, kl + k * 2, ATT_IDESC, true);
            TCGEN05_COMMIT(MBS);
        }

        if (i + 2 < nkt) {
            const char* ks = kimg + (size_t)(i + 2) * 16384;
#pragma unroll
            for (int j = 0; j < 4; j++)
                kreg[j] = *(const uint4*)(ks + tid * 16 + j * 4096);
        }

        // wait O(i-1): frees V smem AND Ph/Pl TMEM for overwrite
        if (i > 0) {
            MBARRIER_WAIT_PARITY(MBO, phO & 1); phO++;
            TCGEN05_FENCE_AFTER();
#pragma unroll
            for (int j = 0; j < 4; j++)
                *(uint4*)(smem + AV + tid * 16 + j * 4096) = vreg[j];
        }

        // ---- softmax: LDTM x32 -> exp -> truncation split -> 4x STTM x8 ----
        {
            uint32_t sr[32];
            TCGEN05_LD_X32(sr, TS_i + cbh);
            TCGEN05_WAIT_LD();
            const bool nomask = (i * 64 + cbh + 31) <= warp_min_qg;
            uint32_t php[16], plp[16];
            if (nomask) {
#pragma unroll
                for (int c = 0; c < 16; c++) {
                    float p0 = ex2f(__uint_as_float(sr[2 * c]));
                    float p1 = ex2f(__uint_as_float(sr[2 * c + 1]));
                    l_part += p0 + p1;
                    split_pair_trunc(p0, p1, php[c], plp[c]);
                }
            } else {
#pragma unroll
                for (int c = 0; c < 16; c++) {
                    int j0 = i * 64 + cbh + 2 * c;
                    float p0 = (j0     <= qg) ? ex2f(__uint_as_float(sr[2 * c]))     : 0.f;
                    float p1 = (j0 + 1 <= qg) ? ex2f(__uint_as_float(sr[2 * c + 1])) : 0.f;
                    l_part += p0 + p1;
                    split_pair_trunc(p0, p1, php[c], plp[c]);
                }
            }
            TCGEN05_ST_X8(PH + (cbh >> 1) + rowoff,     php);
            TCGEN05_ST_X8(PH + (cbh >> 1) + 8 + rowoff, php + 8);
            TCGEN05_ST_X8(PL + (cbh >> 1) + rowoff,     plp);
            TCGEN05_ST_X8(PL + (cbh >> 1) + 8 + rowoff, plp + 8);
        }
        TCGEN05_WAIT_ST();
        FENCE_ASYNC();             // V store visibility
        TCGEN05_FENCE_BEFORE();
        __syncthreads();           // all warps' STTM + V stores done

        // ---- O(i) += Ph*Vh + Pl*Vh + Ph*Vl  (TS mode: A from TMEM) ----
        if (wid == 0 && elect_one_pred()) {
            TCGEN05_FENCE_AFTER();
#pragma unroll
            for (int k = 0; k < 4; k++)
                mma_f16_ts(TO, PH + k * 8, vh + k * 2, ATT_IDESC, !(i == 0 && k == 0));
#pragma unroll
            for (int k = 0; k < 4; k++)
                mma_f16_ts(TO, PL + k * 8, vh + k * 2, ATT_IDESC, true);
#pragma unroll
            for (int k = 0; k < 4; k++)
                mma_f16_ts(TO, PH + k * 8, vl + k * 2, ATT_IDESC, true);
            TCGEN05_COMMIT(MBO);
        }
        if (i + 1 < nkt) {
            const char* vs = vimg + (size_t)(i + 1) * 16384;
#pragma unroll
            for (int j = 0; j < 4; j++)
                vreg[j] = *(const uint4*)(vs + tid * 16 + j * 4096);
        }
    }

    // ---- epilogue: O/l with fused [hi|lo] split store to g_c2 ----
    MBARRIER_WAIT_PARITY(MBO, phO & 1); phO++;
    TCGEN05_FENCE_AFTER();

    float* l_sh = (float*)(smem + ALS);
    l_sh[r_own * 2 + (wid >> 2)] = l_part;
    __syncthreads();
    float linv = 1.f / (l_sh[r_own * 2] + l_sh[r_own * 2 + 1]);

    uint32_t orr[32];
    TCGEN05_LD_X32(orr, TO + cbh);
    TCGEN05_WAIT_LD();
    TCGEN05_FENCE_BEFORE();

    __nv_bfloat16* base = g_c2 + (size_t)(qbase + r_own) * DK2 + colh + cbh;
#pragma unroll
    for (int c = 0; c < 32; c += 4) {
        float f[4];
        __nv_bfloat16 hh[4], ll[4];
#pragma unroll
        for (int e = 0; e < 4; e++) {
            f[e] = __uint_as_float(orr[c + e]) * linv;
            hh[e] = __float2bfloat16_rn(f[e]);
            ll[e] = __float2bfloat16_rn(f[e] - __bfloat162float(hh[e]));
        }
        *(uint2*)(base + c)        = *(uint2*)hh;
        *(uint2*)(base + 1024 + c) = *(uint2*)ll;
    }
    __syncthreads();
    if (tid == 0) { MBARRIER_INVAL(MBS); MBARRIER_INVAL(MBO); }
    __syncthreads();
    if (wid == 0) TCGEN05_DEALLOC(tmem, 256);
#else
    const int qt = 15 - blockIdx.x, bh = blockIdx.y;
    const int b = bh >> 4, h = bh & 15;
    const int r = threadIdx.x >> 1;
    const int d0 = (threadIdx.x & 1) * 32;
    const int qrow = b * SEQ + qt * 128 + r;
    const int qg = qt * 128 + r;
    const float* qp = g_q + (size_t)qrow * DIN + h * HD;
    float o[32];
#pragma unroll
    for (int dd = 0; dd < 32; dd++) o[dd] = 0.f;
    float l = 0.f;
    for (int j = 0; j <= qg; j++) {
        const float* kp = g_k + (size_t)(b * SEQ + j) * DIN + h * HD;
        float s = 0.f;
        for (int d = 0; d < 64; d++) s += qp[d] * kp[d];
        float p = exp2f(s);
        l += p;
        const float* vp = g_v + (size_t)(b * SEQ + j) * DIN + h * HD + d0;
        for (int dd = 0; dd < 32; dd++) o[dd] += p * vp[dd];
    }
    __nv_bfloat16* base = g_c2 + (size_t)qrow * DK2 + h * HD + d0;
    for (int dd = 0; dd < 32; dd++) {
        float f = o[dd] / l;
        __nv_bfloat16 hh = __float2bfloat16_rn(f);
        __nv_bfloat16 ll = __float2bfloat16_rn(f - __bfloat162float(hh));
        base[dd] = hh;
        base[1024 + dd] = ll;
    }
#endif
}

// ==================== launch ====================
extern "C" void kernel_launch(void* const* d_in, const int* in_sizes, int n_in,
                              void* d_out, int out_size) {
    const float* x  = (const float*)d_in[0];
    const float* Wq = (const float*)d_in[1];
    const float* Wk = (const float*)d_in[2];
    const float* Wv = (const float*)d_in[3];
    const float* Wo = (const float*)d_in[4];
    const float* bo = (const float*)d_in[5];
    float* out = (float*)d_out;

    cudaFuncSetAttribute(attn_tc, cudaFuncAttributeMaxDynamicSharedMemorySize, ATT_SMEM);
    cudaFuncSetAttribute(gemm_qkv, cudaFuncAttributeMaxDynamicSharedMemorySize, GEMM_SMEM);
    cudaFuncSetAttribute(gemm_out, cudaFuncAttributeMaxDynamicSharedMemorySize, GEMM_SMEM);

    split_all<<<12288, 256>>>(x, Wq, Wk, Wv, Wo);
    gemm_qkv<<<dim3(4, 32, 3), 256, GEMM_SMEM>>>();
    attn_tc<<<dim3(16, 64), 256, ATT_SMEM>>>();
    gemm_out<<<dim3(4, 32), 256, GEMM_SMEM>>>(out, bo);
}

// round 17
// speedup vs baseline: 1.2951x; 1.0380x over previous
#include <cuda_runtime.h>
#include <cuda_bf16.h>
#include <cstdint>

#define DIN  1024
#define DK2  2048      // [hi | lo] dedup split-K
#define DM   8192      // B*S
#define NH   16
#define HD   64
#define SEQ  2048
#define QSCALE 0.18033688011112042f   // 0.125 * log2(e)

#if defined(__CUDA_ARCH_FEAT_SM103_ALL) || defined(__CUDA_ARCH_FEAT_SM100_ALL)
#define HAS_TCGEN05 1
#else
#define HAS_TCGEN05 0
#endif

// ---------------- scratch (device globals: allocation-free) ----------------
__device__ float g_q[DM * DIN];              // fallback path only
__device__ float g_k[DM * DIN];
__device__ float g_v[DM * DIN];
__device__ __nv_bfloat16 g_x2[DM * DK2];     // [hi | lo]
__device__ __nv_bfloat16 g_c2[DM * DK2];     // ctx split (attn epilogue writes)
__device__ __nv_bfloat16 g_wq2[DIN * DK2];
__device__ __nv_bfloat16 g_wk2[DIN * DK2];
__device__ __nv_bfloat16 g_wv2[DIN * DK2];
__device__ __nv_bfloat16 g_wo2[DIN * DK2];
__device__ char g_kimg[64u * 32u * 16384u];
__device__ char g_vimg[64u * 32u * 16384u];
__device__ char g_qimg[64u * 16u * 32768u];

// ==================== helpers ====================
__device__ __forceinline__ uint32_t smem_to_u32(const void* p) {
    uint32_t a;
    asm("{ .reg .u64 t; cvta.to.shared.u64 t, %1; cvt.u32.u64 %0, t; }" : "=r"(a) : "l"(p));
    return a;
}
#define SMEM_SWIZZLE_128B(o) ((o) ^ (((o) >> 3) & 0x70))

__device__ __forceinline__ float ex2f(float x) {
    float r;
    asm("ex2.approx.f32 %0, %1;" : "=f"(r) : "f"(x));
    return r;
}
// truncation split: hi = top16(f) packed via PRMT; lo = rn(f - hi)
__device__ __forceinline__ void split_pair_trunc(float f0, float f1,
                                                 uint32_t &hi_pair, uint32_t &lo_pair) {
    uint32_t u0 = __float_as_uint(f0), u1 = __float_as_uint(f1);
    asm("prmt.b32 %0, %1, %2, 0x7632;" : "=r"(hi_pair) : "r"(u0), "r"(u1));
    float h0 = __uint_as_float(u0 & 0xFFFF0000u);
    float h1 = __uint_as_float(u1 & 0xFFFF0000u);
    float l0 = f0 - h0, l1 = f1 - h1;
    asm("cvt.rn.bf16x2.f32 %0, %1, %2;" : "=r"(lo_pair) : "f"(l1), "f"(l0));
}

#if HAS_TCGEN05
__device__ __forceinline__ uint32_t elect_one_pred() {
    uint32_t pred;
    asm volatile("{\n\t.reg .pred p;\n\telect.sync _|p, 0xFFFFFFFF;\n\t"
                 "selp.b32 %0, 1, 0, p;\n\t}" : "=r"(pred));
    return pred;
}

static constexpr uint64_t SMEM_DESC_BASE_SW128 =
    (uint64_t(2) << 61) | (uint64_t(1) << 46) | (uint64_t(64) << 32) | (uint64_t(1) << 16);
#define MAKE_SMEM_DESC(a) (SMEM_DESC_BASE_SW128 | ((uint64_t)((a) >> 4) & 0x3FFF))

#define TCGEN05_ALLOC(sr, n) \
    asm volatile("tcgen05.alloc.cta_group::1.sync.aligned.shared::cta.b32 [%0], %1;" \
                 :: "r"((uint32_t)(sr)), "r"((uint32_t)(n)) : "memory")
#define TCGEN05_DEALLOC(t, n) \
    asm volatile("tcgen05.dealloc.cta_group::1.sync.aligned.b32 %0, %1;" :: "r"(t), "r"((uint32_t)(n)))
#define TCGEN05_RELINQUISH() \
    asm volatile("tcgen05.relinquish_alloc_permit.cta_group::1.sync.aligned;")
#define TCGEN05_COMMIT(mb) \
    asm volatile("tcgen05.commit.cta_group::1.mbarrier::arrive::one.shared::cluster.b64 [%0];" \
                 :: "r"((uint32_t)(mb)) : "memory")
#define TCGEN05_WAIT_LD()  asm volatile("tcgen05.wait::ld.sync.aligned;" ::: "memory")
#define TCGEN05_WAIT_ST()  asm volatile("tcgen05.wait::st.sync.aligned;" ::: "memory")
#define TCGEN05_FENCE_BEFORE() asm volatile("tcgen05.fence::before_thread_sync;" ::: "memory")
#define TCGEN05_FENCE_AFTER()  asm volatile("tcgen05.fence::after_thread_sync;" ::: "memory")
#define FENCE_ASYNC() asm volatile("fence.proxy.async.shared::cta;" ::: "memory")

#define CP_ASYNC16(dst, src) \
    asm volatile("cp.async.cg.shared.global [%0], [%1], 16;" \
                 :: "r"((uint32_t)(dst)), "l"(src) : "memory")
#define CP_COMMIT() asm volatile("cp.async.commit_group;" ::: "memory")
#define CP_WAIT(n)  asm volatile("cp.async.wait_group %0;" :: "n"(n) : "memory")

#define MBARRIER_INIT(mb, c) \
    asm volatile("mbarrier.init.shared.b64 [%0], %1;" :: "r"((uint32_t)(mb)), "r"((uint32_t)(c)) : "memory")
#define MBARRIER_INVAL(mb) \
    asm volatile("mbarrier.inval.shared.b64 [%0];" :: "r"((uint32_t)(mb)) : "memory")
#define MBARRIER_WAIT_PARITY(mb, ph) do { \
    uint32_t _mb = (uint32_t)(mb), _p = (uint32_t)(ph), _d; \
    asm volatile("{\n\t.reg .pred p;\n\t" \
        "mbarrier.try_wait.parity.acquire.cta.shared::cta.b64 p, [%1], %2;\n\t" \
        "selp.b32 %0, 1, 0, p;\n\t}" : "=r"(_d) : "r"(_mb), "r"(_p) : "memory"); \
    if (!_d) { \
        asm volatile("{\n\t.reg .pred P1;\n\tWL_%=:\n\t" \
            "mbarrier.try_wait.parity.acquire.cta.shared::cta.b64 P1, [%0], %1, 0x989680;\n\t" \
            "@P1 bra.uni WD_%=;\n\tbra.uni WL_%=;\n\tWD_%=:\n\t}" \
            :: "r"(_mb), "r"(_p) : "memory"); \
    } } while (0)

#define TCGEN05_LD_X32(r, a) \
    asm volatile("tcgen05.ld.sync.aligned.32x32b.x32.b32 " \
        "{%0,%1,%2,%3,%4,%5,%6,%7,%8,%9,%10,%11,%12,%13,%14,%15," \
        "%16,%17,%18,%19,%20,%21,%22,%23,%24,%25,%26,%27,%28,%29,%30,%31}, [%32];" \
        : "=r"((r)[0]),"=r"((r)[1]),"=r"((r)[2]),"=r"((r)[3]),"=r"((r)[4]),"=r"((r)[5]), \
          "=r"((r)[6]),"=r"((r)[7]),"=r"((r)[8]),"=r"((r)[9]),"=r"((r)[10]),"=r"((r)[11]), \
          "=r"((r)[12]),"=r"((r)[13]),"=r"((r)[14]),"=r"((r)[15]),"=r"((r)[16]),"=r"((r)[17]), \
          "=r"((r)[18]),"=r"((r)[19]),"=r"((r)[20]),"=r"((r)[21]),"=r"((r)[22]),"=r"((r)[23]), \
          "=r"((r)[24]),"=r"((r)[25]),"=r"((r)[26]),"=r"((r)[27]),"=r"((r)[28]),"=r"((r)[29]), \
          "=r"((r)[30]),"=r"((r)[31]) : "r"(a))

#define TCGEN05_ST_X8(a, r) \
    asm volatile("tcgen05.st.sync.aligned.32x32b.x8.b32 [%0], " \
        "{%1,%2,%3,%4,%5,%6,%7,%8};" \
        :: "r"(a), "r"((r)[0]), "r"((r)[1]), "r"((r)[2]), "r"((r)[3]), \
           "r"((r)[4]), "r"((r)[5]), "r"((r)[6]), "r"((r)[7]) : "memory")

__device__ __forceinline__ void mma_f16_ss(uint32_t d, uint64_t a, uint64_t b,
                                           uint32_t idesc, bool acc) {
    uint32_t en = acc ? 1u : 0u;
    asm volatile("{\n\t.reg .pred p;\n\tsetp.ne.u32 p, %5, 0;\n\t"
                 "tcgen05.mma.cta_group::1.kind::f16 [%0], %1, %2, %3, {%4,%4,%4,%4}, p;\n\t}"
                 :: "r"(d), "l"(a), "l"(b), "r"(idesc), "r"(0u), "r"(en) : "memory");
}
__device__ __forceinline__ void mma_f16_ts(uint32_t d, uint32_t a_tmem, uint64_t b,
                                           uint32_t idesc, bool acc) {
    uint32_t en = acc ? 1u : 0u;
    asm volatile("{\n\t.reg .pred p;\n\tsetp.ne.u32 p, %5, 0;\n\t"
                 "tcgen05.mma.cta_group::1.kind::f16 [%0], [%1], %2, %3, {%4,%4,%4,%4}, p;\n\t}"
                 :: "r"(d), "r"(a_tmem), "l"(b), "r"(idesc), "r"(0u), "r"(en) : "memory");
}
#endif  // HAS_TCGEN05

// ==================== fp32 -> [hi|lo] bf16 split (grid-stride) ====
__global__ __launch_bounds__(256) void split_all(const float* __restrict__ x,
                                                 const float* __restrict__ Wq,
                                                 const float* __restrict__ Wk,
                                                 const float* __restrict__ Wv,
                                                 const float* __restrict__ Wo) {
#pragma unroll
    for (int it = 0; it < 8; it++) {
        const unsigned vb = blockIdx.x + it * 1536u;   // 12288 virtual blocks
        const float* src; __nv_bfloat16* dst; size_t blk;
        if (vb < 8192) { src = x; dst = g_x2; blk = vb; }
        else {
            int w = (vb - 8192) >> 10;
            blk = (vb - 8192) & 1023;
            switch (w) {
                case 0: src = Wq; dst = g_wq2; break;
                case 1: src = Wk; dst = g_wk2; break;
                case 2: src = Wv; dst = g_wv2; break;
                default: src = Wo; dst = g_wo2; break;
            }
        }
        size_t i = (blk * 256 + threadIdx.x) * 4;
        size_t row = i >> 10;
        int    col = (int)(i & 1023);
        float4 v = *(const float4*)(src + i);
        float f[4] = {v.x, v.y, v.z, v.w};
        __nv_bfloat16 h[4], l[4];
#pragma unroll
        for (int j = 0; j < 4; j++) {
            h[j] = __float2bfloat16_rn(f[j]);
            l[j] = __float2bfloat16_rn(f[j] - __bfloat162float(h[j]));
        }
        __nv_bfloat16* base = dst + row * DK2 + col;
        *(uint2*)(base)        = *(uint2*)h;
        *(uint2*)(base + 1024) = *(uint2*)l;
    }
}

// ==================== tcgen05 projection GEMM: 256x256 tile, TMEM 512 ======
#define GEMM_CHUNKS 16
#define A_OFF0 1024
#define A_OFF1 (1024 + 32768)
#define B_OFF  (1024 + 65536)
#define GEMM_SMEM (1024 + 65536 + 131072)   // 197632
#define GEMM_IDESC 0x8400490u

__device__ __forceinline__ void gemm_core(const __nv_bfloat16* __restrict__ A,
                                          const __nv_bfloat16* __restrict__ B,
                                          float* __restrict__ C,
                                          const float* __restrict__ bias,
                                          int mode) {
#if HAS_TCGEN05
    extern __shared__ char smem[];
    const uint32_t sb = smem_to_u32(smem);
    const int tid = threadIdx.x, wid = tid >> 5, lid = tid & 31;
    const int bm = blockIdx.y * 256;
    const int bn = blockIdx.x * 256;

    const uint32_t TM_PTR = sb, MBH0 = sb + 8, MBH1 = sb + 16;

    if (wid == 0) { TCGEN05_ALLOC(TM_PTR, 512); TCGEN05_RELINQUISH(); }
    if (tid == 0) { MBARRIER_INIT(MBH0, 1); MBARRIER_INIT(MBH1, 1); }
    __syncthreads();
    uint32_t tmem;
    asm volatile("ld.shared.b32 %0, [%1];" : "=r"(tmem) : "r"(TM_PTR));

    auto issue_A = [&](int half, int c) {
        const uint32_t ab = sb + (half ? A_OFF1 : A_OFF0);
        const __nv_bfloat16* Ap = A + (size_t)(bm + half * 128) * DK2 + c * 64;
#pragma unroll
        for (int i = 0; i < 4; i++) {
            int lin = tid + i * 256;
            int row = lin >> 3, q = lin & 7;
            uint32_t sw = SMEM_SWIZZLE_128B(row * 128 + q * 16);
            CP_ASYNC16(ab + sw,         Ap + (size_t)row * DK2 + q * 8);
            CP_ASYNC16(ab + 16384 + sw, Ap + (size_t)row * DK2 + 1024 + q * 8);
        }
    };
    auto issue_B = [&](int c) {
        const uint32_t bb = sb + B_OFF + (c & 1) * 65536;
        const __nv_bfloat16* Bp = B + (size_t)bn * DK2 + c * 64;
#pragma unroll
        for (int i = 0; i < 8; i++) {
            int lin = tid + i * 256;
            int row = lin >> 3, q = lin & 7;
            uint32_t sw = SMEM_SWIZZLE_128B(row * 128 + q * 16);
            CP_ASYNC16(bb + sw,         Bp + (size_t)row * DK2 + q * 8);
            CP_ASYNC16(bb + 32768 + sw, Bp + (size_t)row * DK2 + 1024 + q * 8);
        }
    };
    auto issue_mma = [&](int half, int c) {
        const uint32_t ab = sb + (half ? A_OFF1 : A_OFF0);
        const uint32_t bb = sb + B_OFF + (c & 1) * 65536;
        uint64_t ah = MAKE_SMEM_DESC(ab), al = MAKE_SMEM_DESC(ab + 16384);
        uint64_t bh = MAKE_SMEM_DESC(bb), bl = MAKE_SMEM_DESC(bb + 32768);
        const uint32_t D = tmem + half * 256;
#pragma unroll
        for (int k = 0; k < 4; k++)
            mma_f16_ss(D, ah + k * 2, bh + k * 2, GEMM_IDESC, !(c == 0 && k == 0));
#pragma unroll
        for (int k = 0; k < 4; k++)
            mma_f16_ss(D, al + k * 2, bh + k * 2, GEMM_IDESC, true);
#pragma unroll
        for (int k = 0; k < 4; k++)
            mma_f16_ss(D, ah + k * 2, bl + k * 2, GEMM_IDESC, true);
    };

    issue_A(0, 0); CP_COMMIT();
    issue_B(0);    CP_COMMIT();
    issue_A(1, 0); CP_COMMIT();
    issue_B(1);    CP_COMMIT();

    int ph0 = 0, ph1 = 0;
    for (int c = 0; c < GEMM_CHUNKS; c++) {
        if (c >= 1) {
            MBARRIER_WAIT_PARITY(MBH1, ph1 & 1); ph1++;
            issue_A(1, c); CP_COMMIT();
            if (c + 1 < GEMM_CHUNKS) issue_B(c + 1);
            CP_COMMIT();
        }
        CP_WAIT(2);
        FENCE_ASYNC();
        TCGEN05_FENCE_BEFORE();
        __syncthreads();
        if (wid == 0 && elect_one_pred()) {
            TCGEN05_FENCE_AFTER();
            issue_mma(0, c);
            TCGEN05_COMMIT(MBH0);
        }
        CP_WAIT(1);
        FENCE_ASYNC();
        TCGEN05_FENCE_BEFORE();
        __syncthreads();
        if (wid == 0 && elect_one_pred()) {
            TCGEN05_FENCE_AFTER();
            issue_mma(1, c);
            TCGEN05_COMMIT(MBH1);
        }
        MBARRIER_WAIT_PARITY(MBH0, ph0 & 1); ph0++;
        if (c + 1 < GEMM_CHUNKS) issue_A(0, c + 1);
        CP_COMMIT();
    }
    MBARRIER_WAIT_PARITY(MBH1, ph1 & 1); ph1++;
    TCGEN05_FENCE_AFTER();

    for (int half = 0; half < 2; half++) {
        const uint32_t D = tmem + half * 256;
        const int bmh = bm + half * 128;
        if (mode == 0) {
            if (wid < 4) {
                const int row = bmh + wid * 32 + lid;
                float* Crow = C + (size_t)row * DIN + bn;
#pragma unroll
                for (int cb = 0; cb < 256; cb += 32) {
                    uint32_t r[32];
                    TCGEN05_LD_X32(r, D + cb);
                    TCGEN05_WAIT_LD();
#pragma unroll
                    for (int j = 0; j < 32; j += 4) {
                        float4 v;
                        v.x = __uint_as_float(r[j + 0]) + bias[bn + cb + j + 0];
                        v.y = __uint_as_float(r[j + 1]) + bias[bn + cb + j + 1];
                        v.z = __uint_as_float(r[j + 2]) + bias[bn + cb + j + 2];
                        v.w = __uint_as_float(r[j + 3]) + bias[bn + cb + j + 3];
                        *(float4*)(Crow + cb + j) = v;
                    }
                }
                TCGEN05_FENCE_BEFORE();
            }
        } else {
            char* stg = smem + 1024;
            if (wid < 4) {
                const int rl = wid * 32 + lid;
                const int ktl = rl >> 6, rk = rl & 63;
#pragma unroll
                for (int cb = 0; cb < 256; cb += 32) {
                    uint32_t r[32];
                    TCGEN05_LD_X32(r, D + cb);
                    TCGEN05_WAIT_LD();
                    const int head = cb >> 6;
                    const int hd0  = cb & 63;
                    if (mode == 1) {
                        char* base = stg + head * 32768;
#pragma unroll
                        for (int c = 0; c < 32; c += 2) {
                            float f0 = __uint_as_float(r[c])     * QSCALE;
                            float f1 = __uint_as_float(r[c + 1]) * QSCALE;
                            __nv_bfloat16 hb[2], lb[2];
                            hb[0] = __float2bfloat16_rn(f0);
                            hb[1] = __float2bfloat16_rn(f1);
                            lb[0] = __float2bfloat16_rn(f0 - __bfloat162float(hb[0]));
                            lb[1] = __float2bfloat16_rn(f1 - __bfloat162float(hb[1]));
                            uint32_t off = SMEM_SWIZZLE_128B(rl * 128 + (hd0 + c) * 2);
                            *(uint32_t*)(base + off)         = *(uint32_t*)hb;
                            *(uint32_t*)(base + 16384 + off) = *(uint32_t*)lb;
                        }
                    } else if (mode == 2) {
                        char* base = stg + (head * 2 + ktl) * 16384;
#pragma unroll
                        for (int c = 0; c < 32; c += 2) {
                            float f0 = __uint_as_float(r[c]);
                            float f1 = __uint_as_float(r[c + 1]);
                            __nv_bfloat16 hb[2], lb[2];
                            hb[0] = __float2bfloat16_rn(f0);
                            hb[1] = __float2bfloat16_rn(f1);
                            lb[0] = __float2bfloat16_rn(f0 - __bfloat162float(hb[0]));
                            lb[1] = __float2bfloat16_rn(f1 - __bfloat162float(hb[1]));
                            uint32_t off = SMEM_SWIZZLE_128B(rk * 128 + (hd0 + c) * 2);
                            *(uint32_t*)(base + off)        = *(uint32_t*)hb;
                            *(uint32_t*)(base + 8192 + off) = *(uint32_t*)lb;
                        }
                    } else {
                        char* base = stg + (head * 2 + ktl) * 16384;
#pragma unroll
                        for (int c = 0; c < 32; c++) {
                            float f = __uint_as_float(r[c]);
                            __nv_bfloat16 vh = __float2bfloat16_rn(f);
                            __nv_bfloat16 vl = __float2bfloat16_rn(f - __bfloat162float(vh));
                            uint32_t toff = SMEM_SWIZZLE_128B((hd0 + c) * 128 + rk * 2);
                            *(__nv_bfloat16*)(base + toff)        = vh;
                            *(__nv_bfloat16*)(base + 8192 + toff) = vl;
                        }
                    }
                }
                TCGEN05_FENCE_BEFORE();
            }
            __syncthreads();
            const int bb = bmh >> 11;
            const int h0 = bn >> 6;
            if (mode == 1) {
                const int qt = (bmh & 2047) >> 7;
#pragma unroll
                for (int hh = 0; hh < 4; hh++) {
                    char* dst = g_qimg + (((size_t)(bb * 16 + h0 + hh)) * 16 + qt) * 32768;
                    const char* src = stg + hh * 32768;
#pragma unroll
                    for (int i2 = 0; i2 < 8; i2++)
                        *(uint4*)(dst + tid * 16 + i2 * 4096) =
                            *(const uint4*)(src + tid * 16 + i2 * 4096);
                }
            } else {
                const int kt0 = (bmh & 2047) >> 6;
                char* gimg = (mode == 2) ? g_kimg : g_vimg;
#pragma unroll
                for (int im = 0; im < 8; im++) {
                    int hh = im >> 1, kk = im & 1;
                    char* dst = gimg + (((size_t)(bb * 16 + h0 + hh)) * 32 + kt0 + kk) * 16384;
                    const char* src = stg + im * 16384;
#pragma unroll
                    for (int i2 = 0; i2 < 4; i2++)
                        *(uint4*)(dst + tid * 16 + i2 * 4096) =
                            *(const uint4*)(src + tid * 16 + i2 * 4096);
                }
            }
            __syncthreads();
        }
    }
    __syncthreads();
    if (tid == 0) { MBARRIER_INVAL(MBH0); MBARRIER_INVAL(MBH1); }
    __syncthreads();
    if (wid == 0) TCGEN05_DEALLOC(tmem, 512);
#else
    extern __shared__ char smem[];
    __nv_bfloat16* Achunk = (__nv_bfloat16*)(smem);
    const int tid = threadIdx.x;
    const int bn = blockIdx.x * 256;
    for (int half = 0; half < 2; half++) {
        const int bm = blockIdx.y * 256 + half * 128;
        float acc[128];
        const int nt = tid;
#pragma unroll
        for (int i = 0; i < 128; i++) acc[i] = 0.f;
        for (int c = 0; c < GEMM_CHUNKS; c++) {
            for (int i = tid; i < 128 * 128 / 8; i += 256) {
                int row = i / 16, q = (i % 16) * 8;
                int col = (q < 64) ? (c * 64 + q) : (1024 + c * 64 + q - 64);
                *(uint4*)&Achunk[row * 128 + q] =
                    *(const uint4*)(A + (size_t)(bm + row) * DK2 + col);
            }
            __syncthreads();
            const __nv_bfloat16* Bp = B + (size_t)(bn + nt) * DK2 + c * 64;
            for (int k = 0; k < 64; k++) {
                float bh = __bfloat162float(Bp[k]);
                float bl = __bfloat162float(Bp[1024 + k]);
                for (int m = 0; m < 128; m++) {
                    float ah = __bfloat162float(Achunk[m * 128 + k]);
                    float al = __bfloat162float(Achunk[m * 128 + 64 + k]);
                    acc[m] += ah * bh + al * bh + ah * bl;
                }
            }
            __syncthreads();
        }
        float bbv = (mode == 0) ? bias[bn + nt] : 0.f;
        float sc  = (mode == 1) ? QSCALE : 1.f;
        for (int m = 0; m < 128; m++)
            C[(size_t)(bm + m) * DIN + bn + nt] = acc[m] * sc + bbv;
        __syncthreads();
    }
#endif
}

__global__ __launch_bounds__(256) void gemm_qkv() {
    const __nv_bfloat16* B; float* C; int mode;
    if (blockIdx.z == 0)      { B = g_wq2; C = g_q; mode = 1; }
    else if (blockIdx.z == 1) { B = g_wk2; C = g_k; mode = 2; }
    else                      { B = g_wv2; C = g_v; mode = 3; }
    gemm_core(g_x2, B, C, nullptr, mode);
}
__global__ __launch_bounds__(256) void gemm_out(float* __restrict__ out,
                                                const float* __restrict__ bo) {
    gemm_core(g_c2, g_wo2, out, bo, 0);
}

// ==================== tcgen05 flash attention (cp.async K/V) ===============
// TMEM (256): TS0 @0 | TS1 @64 | TO @128 | Ph @192 | Pl @224
// smem: Q {h|l} 32K | K bufs 2x16K | V bufs 2x16K | ls 1K
#define ATT_IDESC 0x8100490u
#define AQ  1024
#define AK0 (AQ + 32768)            // + buf*16384
#define AV0 (AK0 + 32768)           // + buf*16384
#define ALS (AV0 + 32768)
#define ATT_SMEM (ALS + 1024)       // 99328

__global__ __launch_bounds__(256, 2) void attn_tc() {
#if HAS_TCGEN05
    extern __shared__ char smem[];
    const uint32_t sb = smem_to_u32(smem);
    const int tid = threadIdx.x;
    const int wid = tid >> 5, lane = tid & 31;
    const int qt = 15 - blockIdx.x;
    const int bh = blockIdx.y;
    const int b  = bh >> 4, h = bh & 15;
    const int qbase = b * SEQ + qt * 128;
    const int colh  = h * HD;

    const uint32_t TMP = sb, MBS = sb + 8, MBO = sb + 16;

    if (wid == 0) { TCGEN05_ALLOC(TMP, 256); TCGEN05_RELINQUISH(); }
    if (tid == 0) { MBARRIER_INIT(MBS, 1); MBARRIER_INIT(MBO, 1); }
    __syncthreads();
    uint32_t tmem;
    asm volatile("ld.shared.b32 %0, [%1];" : "=r"(tmem) : "r"(TMP));
    const uint32_t TO = tmem + 128, PH = tmem + 192, PL = tmem + 224;

    const char* qs   = g_qimg + ((size_t)bh * 16 + qt) * 32768;
    const char* kimg = g_kimg + (size_t)bh * 32 * 16384;
    const char* vimg = g_vimg + (size_t)bh * 32 * 16384;

    // ---- prologue via cp.async: C1{Q,K0,V0}, C2{K1}, C3{V1} ----
#pragma unroll
    for (int i = 0; i < 8; i++)
        CP_ASYNC16(sb + AQ + tid * 16 + i * 4096, qs + tid * 16 + i * 4096);
#pragma unroll
    for (int i = 0; i < 4; i++) {
        CP_ASYNC16(sb + AK0 + tid * 16 + i * 4096, kimg + tid * 16 + i * 4096);
        CP_ASYNC16(sb + AV0 + tid * 16 + i * 4096, vimg + tid * 16 + i * 4096);
    }
    CP_COMMIT();    // C1
#pragma unroll
    for (int i = 0; i < 4; i++)
        CP_ASYNC16(sb + AK0 + 16384 + tid * 16 + i * 4096,
                   kimg + 16384 + tid * 16 + i * 4096);
    CP_COMMIT();    // C2
#pragma unroll
    for (int i = 0; i < 4; i++)
        CP_ASYNC16(sb + AV0 + 16384 + tid * 16 + i * 4096,
                   vimg + 16384 + tid * 16 + i * 4096);
    CP_COMMIT();    // C3
    CP_WAIT(2);     // C1 done: Q, K0, V0
    FENCE_ASYNC();
    TCGEN05_FENCE_BEFORE();
    __syncthreads();

    const uint64_t qh = MAKE_SMEM_DESC(sb + AQ), ql = MAKE_SMEM_DESC(sb + AQ + 16384);

    if (wid == 0 && elect_one_pred()) {
        TCGEN05_FENCE_AFTER();
        uint64_t kh = MAKE_SMEM_DESC(sb + AK0), kl = MAKE_SMEM_DESC(sb + AK0 + 8192);
#pragma unroll
        for (int k = 0; k < 4; k++) mma_f16_ss(tmem, qh + k * 2, kh + k * 2, ATT_IDESC, k > 0);
#pragma unroll
        for (int k = 0; k < 4; k++) mma_f16_ss(tmem, ql + k * 2, kh + k * 2, ATT_IDESC, true);
#pragma unroll
        for (int k = 0; k < 4; k++) mma_f16_ss(tmem, qh + k * 2, kl + k * 2, ATT_IDESC, true);
        TCGEN05_COMMIT(MBS);
    }

    const int nkt = 2 * qt + 2;
    const int r_own = (wid & 3) * 32 + lane;
    const int cbh   = (wid >> 2) * 32;
    const uint32_t rowoff = (uint32_t)(wid & 3) << 21;
    const int qg    = qt * 128 + r_own;
    const int warp_min_qg = qt * 128 + (wid & 3) * 32;
    float l_part = 0.f;
    int phS = 0, phO = 0;

    for (int i = 0; i < nkt; i++) {
        const uint32_t TS_i = tmem + (i & 1) * 64;
        const uint32_t TS_n = tmem + ((i + 1) & 1) * 64;
        const uint32_t KBn  = sb + AK0 + ((i + 1) & 1) * 16384;
        const uint32_t VBi  = sb + AV0 + (i & 1) * 16384;

        // 1. S(i) done -> Kbuf(i&1) free
        MBARRIER_WAIT_PARITY(MBS, phS & 1); phS++;
        TCGEN05_FENCE_AFTER();

        // 2. cp.async K(i+2) -> Kbuf(i&1)  [K-group, maybe empty]
        if (i + 2 < nkt) {
            const char* ks = kimg + (size_t)(i + 2) * 16384;
            const uint32_t kd = sb + AK0 + (i & 1) * 16384;
#pragma unroll
            for (int j = 0; j < 4; j++)
                CP_ASYNC16(kd + tid * 16 + j * 4096, ks + tid * 16 + j * 4096);
        }
        CP_COMMIT();

        // 3. ensure K(i+1) landed (2 groups back)
        CP_WAIT(2);
        FENCE_ASYNC();
        TCGEN05_FENCE_BEFORE();
        __syncthreads();

        // 4. issue S(i+1)
        if (i + 1 < nkt && wid == 0 && elect_one_pred()) {
            TCGEN05_FENCE_AFTER();
            uint64_t khn = MAKE_SMEM_DESC(KBn), kln = MAKE_SMEM_DESC(KBn + 8192);
#pragma unroll
            for (int k = 0; k < 4; k++) mma_f16_ss(TS_n, qh + k * 2, khn + k * 2, ATT_IDESC, k > 0);
#pragma unroll
            for (int k = 0; k < 4; k++) mma_f16_ss(TS_n, ql + k * 2, khn + k * 2, ATT_IDESC, true);
#pragma unroll
            for (int k = 0; k < 4; k++) mma_f16_ss(TS_n, qh + k * 2, kln + k * 2, ATT_IDESC, true);
            TCGEN05_COMMIT(MBS);
        }

        // 5. O(i-1) done -> Vbuf((i+1)&1) free; cp.async V(i+1)  [V-group]
        if (i > 0) {
            MBARRIER_WAIT_PARITY(MBO, phO & 1); phO++;
            TCGEN05_FENCE_AFTER();
        }
        if (i > 0 && i + 1 < nkt) {
            const char* vs = vimg + (size_t)(i + 1) * 16384;
            const uint32_t vd = sb + AV0 + ((i + 1) & 1) * 16384;
#pragma unroll
            for (int j = 0; j < 4; j++)
                CP_ASYNC16(vd + tid * 16 + j * 4096, vs + tid * 16 + j * 4096);
        }
        CP_COMMIT();

        // 6. softmax: LDTM x32 -> exp -> truncation split -> STTM
        {
            uint32_t sr[32];
            TCGEN05_LD_X32(sr, TS_i + cbh);
            TCGEN05_WAIT_LD();
            const bool nomask = (i * 64 + cbh + 31) <= warp_min_qg;
            uint32_t php[16], plp[16];
            if (nomask) {
#pragma unroll
                for (int c = 0; c < 16; c++) {
                    float p0 = ex2f(__uint_as_float(sr[2 * c]));
                    float p1 = ex2f(__uint_as_float(sr[2 * c + 1]));
                    l_part += p0 + p1;
                    split_pair_trunc(p0, p1, php[c], plp[c]);
                }
            } else {
#pragma unroll
                for (int c = 0; c < 16; c++) {
                    int j0 = i * 64 + cbh + 2 * c;
                    float p0 = (j0     <= qg) ? ex2f(__uint_as_float(sr[2 * c]))     : 0.f;
                    float p1 = (j0 + 1 <= qg) ? ex2f(__uint_as_float(sr[2 * c + 1])) : 0.f;
                    l_part += p0 + p1;
                    split_pair_trunc(p0, p1, php[c], plp[c]);
                }
            }
            TCGEN05_ST_X8(PH + (cbh >> 1) + rowoff,     php);
            TCGEN05_ST_X8(PH + (cbh >> 1) + 8 + rowoff, php + 8);
            TCGEN05_ST_X8(PL + (cbh >> 1) + rowoff,     plp);
            TCGEN05_ST_X8(PL + (cbh >> 1) + 8 + rowoff, plp + 8);
        }
        TCGEN05_WAIT_ST();

        // 7. ensure V(i) landed (2 groups back) + all warps' P in TMEM
        CP_WAIT(2);
        FENCE_ASYNC();
        TCGEN05_FENCE_BEFORE();
        __syncthreads();

        // 8. O(i) += Ph*Vh + Pl*Vh + Ph*Vl  (TS mode)
        if (wid == 0 && elect_one_pred()) {
            TCGEN05_FENCE_AFTER();
            uint64_t vhi = MAKE_SMEM_DESC(VBi), vli = MAKE_SMEM_DESC(VBi + 8192);
#pragma unroll
            for (int k = 0; k < 4; k++)
                mma_f16_ts(TO, PH + k * 8, vhi + k * 2, ATT_IDESC, !(i == 0 && k == 0));
#pragma unroll
            for (int k = 0; k < 4; k++)
                mma_f16_ts(TO, PL + k * 8, vhi + k * 2, ATT_IDESC, true);
#pragma unroll
            for (int k = 0; k < 4; k++)
                mma_f16_ts(TO, PH + k * 8, vli + k * 2, ATT_IDESC, true);
            TCGEN05_COMMIT(MBO);
        }
    }

    // ---- epilogue: O/l with fused [hi|lo] split store to g_c2 ----
    MBARRIER_WAIT_PARITY(MBO, phO & 1); phO++;
    TCGEN05_FENCE_AFTER();

    float* l_sh = (float*)(smem + ALS);
    l_sh[r_own * 2 + (wid >> 2)] = l_part;
    __syncthreads();
    float linv = 1.f / (l_sh[r_own * 2] + l_sh[r_own * 2 + 1]);

    uint32_t orr[32];
    TCGEN05_LD_X32(orr, TO + cbh);
    TCGEN05_WAIT_LD();
    TCGEN05_FENCE_BEFORE();

    __nv_bfloat16* base = g_c2 + (size_t)(qbase + r_own) * DK2 + colh + cbh;
#pragma unroll
    for (int c = 0; c < 32; c += 4) {
        float f[4];
        __nv_bfloat16 hh[4], ll[4];
#pragma unroll
        for (int e = 0; e < 4; e++) {
            f[e] = __uint_as_float(orr[c + e]) * linv;
            hh[e] = __float2bfloat16_rn(f[e]);
            ll[e] = __float2bfloat16_rn(f[e] - __bfloat162float(hh[e]));
        }
        *(uint2*)(base + c)        = *(uint2*)hh;
        *(uint2*)(base + 1024 + c) = *(uint2*)ll;
    }
    __syncthreads();
    if (tid == 0) { MBARRIER_INVAL(MBS); MBARRIER_INVAL(MBO); }
    __syncthreads();
    if (wid == 0) TCGEN05_DEALLOC(tmem, 256);
#else
    const int qt = 15 - blockIdx.x, bh = blockIdx.y;
    const int b = bh >> 4, h = bh & 15;
    const int r = threadIdx.x >> 1;
    const int d0 = (threadIdx.x & 1) * 32;
    const int qrow = b * SEQ + qt * 128 + r;
    const int qg = qt * 128 + r;
    const float* qp = g_q + (size_t)qrow * DIN + h * HD;
    float o[32];
#pragma unroll
    for (int dd = 0; dd < 32; dd++) o[dd] = 0.f;
    float l = 0.f;
    for (int j = 0; j <= qg; j++) {
        const float* kp = g_k + (size_t)(b * SEQ + j) * DIN + h * HD;
        float s = 0.f;
        for (int d = 0; d < 64; d++) s += qp[d] * kp[d];
        float p = exp2f(s);
        l += p;
        const float* vp = g_v + (size_t)(b * SEQ + j) * DIN + h * HD + d0;
        for (int dd = 0; dd < 32; dd++) o[dd] += p * vp[dd];
    }
    __nv_bfloat16* base = g_c2 + (size_t)qrow * DK2 + h * HD + d0;
    for (int dd = 0; dd < 32; dd++) {
        float f = o[dd] / l;
        __nv_bfloat16 hh = __float2bfloat16_rn(f);
        __nv_bfloat16 ll = __float2bfloat16_rn(f - __bfloat162float(hh));
        base[dd] = hh;
        base[1024 + dd] = ll;
    }
#endif
}

// ==================== launch ====================
extern "C" void kernel_launch(void* const* d_in, const int* in_sizes, int n_in,
                              void* d_out, int out_size) {
    const float* x  = (const float*)d_in[0];
    const float* Wq = (const float*)d_in[1];
    const float* Wk = (const float*)d_in[2];
    const float* Wv = (const float*)d_in[3];
    const float* Wo = (const float*)d_in[4];
    const float* bo = (const float*)d_in[5];
    float* out = (float*)d_out;

    cudaFuncSetAttribute(attn_tc, cudaFuncAttributeMaxDynamicSharedMemorySize, ATT_SMEM);
    cudaFuncSetAttribute(gemm_qkv, cudaFuncAttributeMaxDynamicSharedMemorySize, GEMM_SMEM);
    cudaFuncSetAttribute(gemm_out, cudaFuncAttributeMaxDynamicSharedMemorySize, GEMM_SMEM);

    split_all<<<1536, 256>>>(x, Wq, Wk, Wv, Wo);
    gemm_qkv<<<dim3(4, 32, 3), 256, GEMM_SMEM>>>();
    attn_tc<<<dim3(16, 64), 256, ATT_SMEM>>>();
    gemm_out<<<dim3(4, 32), 256, GEMM_SMEM>>>(out, bo);
}